// round 7
// baseline (speedup 1.0000x reference)
#include <cuda_runtime.h>
#include <math.h>

// Problem constants (fixed shapes)
#define NN 20000
#define EE 320000
#define CC 64

// ---------------- scratch (device globals; no allocation allowed) ----------------
__device__ __align__(16) float g_s[NN * CC];            // up-projected scalars  s[n][c]
__device__ __align__(16) float g_v[NN * CC * 3];        // up-projected vectors  v[n][c][m]
__device__ __align__(16) float g_skip_s[NN * 2 * CC];   // skip_s[n][o], o<128
__device__ __align__(16) float g_skip_v[NN * CC * 3];   // skip_v[n][o][m]
__device__ __align__(16) float g_agg_s[NN * 2 * CC];    // agg_s[n][j], j<128 (raw sums)
__device__ __align__(16) float g_agg_v[NN * 3 * 2 * CC];// agg_v[n][m][c2], c2<128 (raw sums)

__device__ __forceinline__ float swishf(float x) { return x / (1.0f + __expf(-x)); }

__device__ __forceinline__ void red4(float* p, float a, float b, float c, float d) {
    asm volatile("red.global.add.v4.f32 [%0], {%1,%2,%3,%4};"
                 :: "l"(p), "f"(a), "f"(b), "f"(c), "f"(d) : "memory");
}

// ---------------- kernel: zero aggregation buffers ----------------
__global__ void k_zero() {
    float4 z = make_float4(0.f, 0.f, 0.f, 0.f);
    int n1 = NN * 2 * CC / 4;
    for (int i = blockIdx.x * blockDim.x + threadIdx.x; i < n1; i += gridDim.x * blockDim.x)
        reinterpret_cast<float4*>(g_agg_s)[i] = z;
    int n2 = NN * 6 * CC / 4;
    for (int i = blockIdx.x * blockDim.x + threadIdx.x; i < n2; i += gridDim.x * blockDim.x)
        reinterpret_cast<float4*>(g_agg_v)[i] = z;
}

// ---------------- kernel: node up-projection ----------------
__global__ void __launch_bounds__(256) k_up(const float* __restrict__ scal,
                                            const float* __restrict__ nvec,
                                            const float* __restrict__ Wus,
                                            const float* __restrict__ Wuv) {
    extern __shared__ float sm[];
    float* sWs = sm;          // 64*64
    float* sWv = sm + 4096;   // 64*64
    float* sBuf = sm + 8192;  // 8 warps * 256
    int tid = threadIdx.x, wid = tid >> 5, l = tid & 31;
    for (int i = tid; i < 4096; i += 256) { sWs[i] = Wus[i]; sWv[i] = Wuv[i]; }
    __syncthreads();
    float* sc = sBuf + wid * 256;  // 64 scalars
    float* vb = sc + 64;           // 192 vector components [k*3+m]
    int nwarp = gridDim.x * 8;
    for (int n = blockIdx.x * 8 + wid; n < NN; n += nwarp) {
        sc[l] = scal[n * 64 + l];
        sc[l + 32] = scal[n * 64 + l + 32];
#pragma unroll
        for (int q = 0; q < 6; q++) vb[l + q * 32] = nvec[n * 192 + l + q * 32];
        __syncwarp();
        float a0 = 0.f, a1 = 0.f;
#pragma unroll
        for (int k = 0; k < 64; k++) {
            float a = sc[k];
            a0 = fmaf(a, sWs[k * 64 + l], a0);
            a1 = fmaf(a, sWs[k * 64 + l + 32], a1);
        }
        g_s[n * 64 + l] = a0;
        g_s[n * 64 + l + 32] = a1;
        float v0[3] = {0.f, 0.f, 0.f}, v1[3] = {0.f, 0.f, 0.f};
#pragma unroll
        for (int k = 0; k < 64; k++) {
            float w0 = sWv[k * 64 + l], w1 = sWv[k * 64 + l + 32];
#pragma unroll
            for (int m = 0; m < 3; m++) {
                float a = vb[k * 3 + m];
                v0[m] = fmaf(a, w0, v0[m]);
                v1[m] = fmaf(a, w1, v1[m]);
            }
        }
#pragma unroll
        for (int m = 0; m < 3; m++) {
            g_v[n * 192 + l * 3 + m] = v0[m];
            g_v[n * 192 + (l + 32) * 3 + m] = v1[m];
        }
        __syncwarp();
    }
}

// ---------------- kernel: per-species skip projections ----------------
__global__ void __launch_bounds__(256) k_skip(const float* __restrict__ scal,
                                              const float* __restrict__ nvec,
                                              const int* __restrict__ specie,
                                              const float* __restrict__ Wss,
                                              const float* __restrict__ Wsv) {
    extern __shared__ float sm[];
    float* sS = sm;            // 4*64*128 = 32768
    float* sV = sm + 32768;    // 4*64*64  = 16384
    float* sBuf = sm + 49152;  // 8 * 256
    int tid = threadIdx.x, wid = tid >> 5, l = tid & 31;
    for (int i = tid; i < 32768; i += 256) sS[i] = Wss[i];
    for (int i = tid; i < 16384; i += 256) sV[i] = Wsv[i];
    __syncthreads();
    float* sc = sBuf + wid * 256;
    float* vb = sc + 64;
    int nwarp = gridDim.x * 8;
    for (int n = blockIdx.x * 8 + wid; n < NN; n += nwarp) {
        sc[l] = scal[n * 64 + l];
        sc[l + 32] = scal[n * 64 + l + 32];
#pragma unroll
        for (int q = 0; q < 6; q++) vb[l + q * 32] = nvec[n * 192 + l + q * 32];
        __syncwarp();
        int sp = specie[n];
        const float* ws = sS + sp * 8192;
        const float* wv = sV + sp * 4096;
        float a0 = 0.f, a1 = 0.f, a2 = 0.f, a3 = 0.f;
#pragma unroll
        for (int k = 0; k < 64; k++) {
            float x = sc[k];
            const float* w = ws + k * 128;
            a0 = fmaf(x, w[l], a0);
            a1 = fmaf(x, w[l + 32], a1);
            a2 = fmaf(x, w[l + 64], a2);
            a3 = fmaf(x, w[l + 96], a3);
        }
        g_skip_s[n * 128 + l] = a0;
        g_skip_s[n * 128 + l + 32] = a1;
        g_skip_s[n * 128 + l + 64] = a2;
        g_skip_s[n * 128 + l + 96] = a3;
        float v0[3] = {0.f, 0.f, 0.f}, v1[3] = {0.f, 0.f, 0.f};
#pragma unroll
        for (int k = 0; k < 64; k++) {
            float w0 = wv[k * 64 + l], w1 = wv[k * 64 + l + 32];
#pragma unroll
            for (int m = 0; m < 3; m++) {
                float a = vb[k * 3 + m];
                v0[m] = fmaf(a, w0, v0[m]);
                v1[m] = fmaf(a, w1, v1[m]);
            }
        }
#pragma unroll
        for (int m = 0; m < 3; m++) {
            g_skip_v[n * 192 + l * 3 + m] = v0[m];
            g_skip_v[n * 192 + (l + 32) * 3 + m] = v1[m];
        }
        __syncwarp();
    }
}

// ---------------- kernel: edges (features -> MLP -> messages -> scatter) ----------------
// 64-edge tiles, 256 threads, 2 blocks/SM. Activations TRANSPOSED [k][e] (EPAD=76,
// 16B aligned) so GEMM k-loops read each thread's 8 edges as 2x LDS.128 (the 256B-
// unique-data wavefront floor) instead of 8 strided scalar LDS with conflicts.
// thread mapping: og = tid>>3 (0..31), eg = tid&7.
#define EPAD 76

__global__ void __launch_bounds__(256, 2) k_edge(const float* __restrict__ vectors,
                                                 const int* __restrict__ senders,
                                                 const int* __restrict__ receivers,
                                                 const float* __restrict__ W0,
                                                 const float* __restrict__ W1,
                                                 const float* __restrict__ W2) {
    extern __shared__ float sm[];
    float* sW0 = sm;                 // 512
    float* sW1 = sm + 512;           // 4096
    float* sW2 = sm + 4608;          // 16384
    float* sH  = sm + 20992;         // 64*76 = 4864, transposed [k][e], reused H0->H1
    float* sFT = sm + 25856;         // 8*76  = 608, transposed [b][e]
    float* sYb = sm + 26464;         // 64*4  = 256
    int* sSend = (int*)(sm + 26720); // 64
    int* sRecv = sSend + 64;         // 64  -> total 26848 floats = 107392 B

    int tid = threadIdx.x;
    for (int i = tid; i < 512; i += 256) sW0[i] = W0[i];
    for (int i = tid; i < 4096; i += 256) sW1[i] = W1[i];
    for (int i = tid; i < 16384; i += 256) sW2[i] = W2[i];
    __syncthreads();

    const int og = tid >> 3;  // 0..31
    const int eg = tid & 7;   // 0..7
    const float SQRT2 = 1.41421356237309515f;
    const float SQRT3 = 1.73205080756887729f;
    const float INV_SQRT3 = 0.57735026918962576f;
    const float PI = 3.14159265358979323846f;

    int ntile = EE / 64;
    for (int t = blockIdx.x; t < ntile; t += gridDim.x) {
        int e0 = t * 64;
        // ---- phase 1: per-edge features (threads 0..63) ----
        if (tid < 64) {
            int e = e0 + tid;
            float vx = vectors[e * 3 + 0];
            float vy = vectors[e * 3 + 1];
            float vz = vectors[e * 3 + 2];
            float x = sqrtf(vx * vx + vy * vy + vz * vz);
            float sx = (x == 0.f) ? 1.f : x;
            float inv = 1.f / sx;
            sYb[tid * 4 + 0] = SQRT3 * vx * inv;
            sYb[tid * 4 + 1] = SQRT3 * vy * inv;
            sYb[tid * 4 + 2] = SQRT3 * vz * inv;
            float u = fminf(x, 1.f);
            float u2 = u * u, u3 = u2 * u, u6 = u3 * u3, u7 = u6 * u, u8 = u7 * u;
            float env = (x < 1.f) ? (1.f - 28.f * u6 + 48.f * u7 - 21.f * u8) : 0.f;
            float s1, c1;
            sincosf(PI * x, &s1, &c1);
            float pref = SQRT2 * inv * env;
            float sn = s1, cn = c1;
            sFT[0 * EPAD + tid] = pref * sn;
#pragma unroll
            for (int b = 1; b < 8; b++) {
                float sn1 = sn * c1 + cn * s1;
                float cn1 = cn * c1 - sn * s1;
                sn = sn1; cn = cn1;
                sFT[b * EPAD + tid] = pref * sn;
            }
            sSend[tid] = senders[e];
            sRecv[tid] = receivers[e];
        }
        __syncthreads();

        // ---- phase 2: h0 = swish(feat @ W0) -> sH (transposed) ----
        {
            float a0[8], a1[8];
#pragma unroll
            for (int i = 0; i < 8; i++) { a0[i] = 0.f; a1[i] = 0.f; }
#pragma unroll
            for (int b = 0; b < 8; b++) {
                float4 f0 = *reinterpret_cast<const float4*>(sFT + b * EPAD + eg * 8);
                float4 f1 = *reinterpret_cast<const float4*>(sFT + b * EPAD + eg * 8 + 4);
                float w0 = sW0[b * 64 + og];
                float w1 = sW0[b * 64 + og + 32];
                float ff[8] = {f0.x, f0.y, f0.z, f0.w, f1.x, f1.y, f1.z, f1.w};
#pragma unroll
                for (int i = 0; i < 8; i++) {
                    a0[i] = fmaf(ff[i], w0, a0[i]);
                    a1[i] = fmaf(ff[i], w1, a1[i]);
                }
            }
#pragma unroll
            for (int i = 0; i < 8; i++) {
                sH[og * EPAD + eg * 8 + i] = swishf(a0[i]);
                sH[(og + 32) * EPAD + eg * 8 + i] = swishf(a1[i]);
            }
        }
        __syncthreads();

        // ---- phase 3: h1 = swish(h0 @ W1), in place into sH ----
        {
            float a0[8], a1[8];
#pragma unroll
            for (int i = 0; i < 8; i++) { a0[i] = 0.f; a1[i] = 0.f; }
#pragma unroll 4
            for (int k = 0; k < 64; k++) {
                float4 h0 = *reinterpret_cast<const float4*>(sH + k * EPAD + eg * 8);
                float4 h1 = *reinterpret_cast<const float4*>(sH + k * EPAD + eg * 8 + 4);
                float w0 = sW1[k * 64 + og];
                float w1 = sW1[k * 64 + og + 32];
                float hh[8] = {h0.x, h0.y, h0.z, h0.w, h1.x, h1.y, h1.z, h1.w};
#pragma unroll
                for (int i = 0; i < 8; i++) {
                    a0[i] = fmaf(hh[i], w0, a0[i]);
                    a1[i] = fmaf(hh[i], w1, a1[i]);
                }
            }
            __syncthreads();  // everyone done READING h0 before in-place overwrite
#pragma unroll
            for (int i = 0; i < 8; i++) {
                sH[og * EPAD + eg * 8 + i] = swishf(a0[i]);
                sH[(og + 32) * EPAD + eg * 8 + i] = swishf(a1[i]);
            }
        }
        __syncthreads();

        // ---- phase 4: mix = h1 @ W2  [64x64]@[64x256], thread tile 8e x 8j ----
        float acc[8][8];
#pragma unroll
        for (int i = 0; i < 8; i++)
#pragma unroll
            for (int q = 0; q < 8; q++) acc[i][q] = 0.f;
        {
            const int j0 = og * 8;
#pragma unroll 4
            for (int k = 0; k < 64; k++) {
                float4 h0 = *reinterpret_cast<const float4*>(sH + k * EPAD + eg * 8);
                float4 h1 = *reinterpret_cast<const float4*>(sH + k * EPAD + eg * 8 + 4);
                float4 b0 = *reinterpret_cast<const float4*>(sW2 + k * 256 + j0);
                float4 b1 = *reinterpret_cast<const float4*>(sW2 + k * 256 + j0 + 4);
                float hh[8] = {h0.x, h0.y, h0.z, h0.w, h1.x, h1.y, h1.z, h1.w};
#pragma unroll
                for (int i = 0; i < 8; i++) {
                    acc[i][0] = fmaf(hh[i], b0.x, acc[i][0]);
                    acc[i][1] = fmaf(hh[i], b0.y, acc[i][1]);
                    acc[i][2] = fmaf(hh[i], b0.z, acc[i][2]);
                    acc[i][3] = fmaf(hh[i], b0.w, acc[i][3]);
                    acc[i][4] = fmaf(hh[i], b1.x, acc[i][4]);
                    acc[i][5] = fmaf(hh[i], b1.y, acc[i][5]);
                    acc[i][6] = fmaf(hh[i], b1.z, acc[i][6]);
                    acc[i][7] = fmaf(hh[i], b1.w, acc[i][7]);
                }
            }
        }

        // ---- phase 5: messages + vectored scatter-add ----
        {
            const int r = og >> 3;
            const int c0 = (og & 7) * 8;
#pragma unroll 1
            for (int i = 0; i < 8; i++) {
                int e = eg * 8 + i;
                int snd = sSend[e];
                int rcv = sRecv[e];
                float* mx = acc[i];
                if (r == 0) {
                    const float4* sp = reinterpret_cast<const float4*>(g_s + snd * 64 + c0);
                    float4 m0 = sp[0], m1 = sp[1];
                    red4(g_agg_s + rcv * 128 + c0,
                         m0.x * mx[0], m0.y * mx[1], m0.z * mx[2], m0.w * mx[3]);
                    red4(g_agg_s + rcv * 128 + c0 + 4,
                         m1.x * mx[4], m1.y * mx[5], m1.z * mx[6], m1.w * mx[7]);
                } else if (r == 1) {
                    float y0 = sYb[e * 4 + 0], y1 = sYb[e * 4 + 1], y2 = sYb[e * 4 + 2];
                    const float4* vp = reinterpret_cast<const float4*>(g_v + snd * 192 + c0 * 3);
                    float mv[24];
#pragma unroll
                    for (int q = 0; q < 6; q++) {
                        float4 f = vp[q];
                        mv[q * 4 + 0] = f.x; mv[q * 4 + 1] = f.y;
                        mv[q * 4 + 2] = f.z; mv[q * 4 + 3] = f.w;
                    }
                    float tq[8];
#pragma unroll
                    for (int q = 0; q < 8; q++)
                        tq[q] = (mv[q * 3] * y0 + mv[q * 3 + 1] * y1 + mv[q * 3 + 2] * y2) * INV_SQRT3 * mx[q];
                    red4(g_agg_s + rcv * 128 + 64 + c0, tq[0], tq[1], tq[2], tq[3]);
                    red4(g_agg_s + rcv * 128 + 64 + c0 + 4, tq[4], tq[5], tq[6], tq[7]);
                } else if (r == 2) {
                    const float4* vp = reinterpret_cast<const float4*>(g_v + snd * 192 + c0 * 3);
                    float mv[24];
#pragma unroll
                    for (int q = 0; q < 6; q++) {
                        float4 f = vp[q];
                        mv[q * 4 + 0] = f.x; mv[q * 4 + 1] = f.y;
                        mv[q * 4 + 2] = f.z; mv[q * 4 + 3] = f.w;
                    }
#pragma unroll
                    for (int m = 0; m < 3; m++) {
                        red4(g_agg_v + rcv * 384 + m * 128 + c0,
                             mv[0 * 3 + m] * mx[0], mv[1 * 3 + m] * mx[1],
                             mv[2 * 3 + m] * mx[2], mv[3 * 3 + m] * mx[3]);
                        red4(g_agg_v + rcv * 384 + m * 128 + c0 + 4,
                             mv[4 * 3 + m] * mx[4], mv[5 * 3 + m] * mx[5],
                             mv[6 * 3 + m] * mx[6], mv[7 * 3 + m] * mx[7]);
                    }
                } else {
                    float y[3] = {sYb[e * 4 + 0], sYb[e * 4 + 1], sYb[e * 4 + 2]};
                    const float4* sp = reinterpret_cast<const float4*>(g_s + snd * 64 + c0);
                    float4 m0 = sp[0], m1 = sp[1];
                    float msv[8] = {m0.x * mx[0], m0.y * mx[1], m0.z * mx[2], m0.w * mx[3],
                                    m1.x * mx[4], m1.y * mx[5], m1.z * mx[6], m1.w * mx[7]};
#pragma unroll
                    for (int m = 0; m < 3; m++) {
                        red4(g_agg_v + rcv * 384 + m * 128 + 64 + c0,
                             msv[0] * y[m], msv[1] * y[m], msv[2] * y[m], msv[3] * y[m]);
                        red4(g_agg_v + rcv * 384 + m * 128 + 64 + c0 + 4,
                             msv[4] * y[m], msv[5] * y[m], msv[6] * y[m], msv[7] * y[m]);
                    }
                }
            }
        }
        __syncthreads();  // protect sFT/sYb/sSend/sH before next tile
    }
}

// ---------------- kernel: final down-projection + skip + gating + output ----------------
__global__ void __launch_bounds__(256) k_final(const float* __restrict__ Wds,
                                               const float* __restrict__ Wdv,
                                               float* __restrict__ out) {
    extern __shared__ float sm[];
    float* sWs = sm;            // 128*128 = 16384
    float* sWv = sm + 16384;    // 128*64  = 8192
    float* sBuf = sm + 24576;   // 8 * 520
    int tid = threadIdx.x, wid = tid >> 5, l = tid & 31;
    for (int i = tid; i < 16384; i += 256) sWs[i] = Wds[i];
    for (int i = tid; i < 8192; i += 256) sWv[i] = Wdv[i];
    __syncthreads();
    float* As = sBuf + wid * 520;  // 128: agg_s
    float* Av = As + 128;          // 384: agg_v [m][128]
    const float INV = 0.25f;       // 1/sqrt(16)
    int nwarp = gridDim.x * 8;
    for (int n = blockIdx.x * 8 + wid; n < NN; n += nwarp) {
#pragma unroll
        for (int q = 0; q < 4; q++) As[l + 32 * q] = g_agg_s[n * 128 + l + 32 * q];
#pragma unroll
        for (int q = 0; q < 12; q++) Av[l + 32 * q] = g_agg_v[n * 384 + l + 32 * q];
        __syncwarp();
        float a0 = 0.f, a1 = 0.f, a2 = 0.f, a3 = 0.f;
#pragma unroll 4
        for (int k = 0; k < 128; k++) {
            float x = As[k];
            const float* w = sWs + k * 128;
            a0 = fmaf(x, w[l], a0);
            a1 = fmaf(x, w[l + 32], a1);
            a2 = fmaf(x, w[l + 64], a2);
            a3 = fmaf(x, w[l + 96], a3);
        }
        float os0 = INV * a0 + g_skip_s[n * 128 + l];
        float os1 = INV * a1 + g_skip_s[n * 128 + l + 32];
        float os2 = INV * a2 + g_skip_s[n * 128 + l + 64];
        float os3 = INV * a3 + g_skip_s[n * 128 + l + 96];
        float scal0 = swishf(os0), scal1 = swishf(os1);
        float gate0 = swishf(os2), gate1 = swishf(os3);
        float v0[3] = {0.f, 0.f, 0.f}, v1[3] = {0.f, 0.f, 0.f};
#pragma unroll 4
        for (int k = 0; k < 128; k++) {
            float w0 = sWv[k * 64 + l], w1 = sWv[k * 64 + l + 32];
#pragma unroll
            for (int m = 0; m < 3; m++) {
                float a = Av[m * 128 + k];
                v0[m] = fmaf(a, w0, v0[m]);
                v1[m] = fmaf(a, w1, v1[m]);
            }
        }
        out[n * 256 + l] = scal0;
        out[n * 256 + l + 32] = scal1;
#pragma unroll
        for (int m = 0; m < 3; m++) {
            float ov0 = INV * v0[m] + g_skip_v[n * 192 + l * 3 + m];
            float ov1 = INV * v1[m] + g_skip_v[n * 192 + (l + 32) * 3 + m];
            out[n * 256 + 64 + l * 3 + m] = ov0 * gate0;
            out[n * 256 + 64 + (l + 32) * 3 + m] = ov1 * gate1;
        }
        __syncwarp();
    }
}

// ---------------- launch ----------------
extern "C" void kernel_launch(void* const* d_in, const int* in_sizes, int n_in,
                              void* d_out, int out_size) {
    const float* vectors      = (const float*)d_in[0];
    const float* node_scalars = (const float*)d_in[1];
    const float* node_vectors = (const float*)d_in[2];
    const int*   node_specie  = (const int*)d_in[3];
    const int*   senders      = (const int*)d_in[4];
    const int*   receivers    = (const int*)d_in[5];
    const float* W_skip_s     = (const float*)d_in[6];
    const float* W_skip_v     = (const float*)d_in[7];
    const float* W_up_s       = (const float*)d_in[8];
    const float* W_up_v       = (const float*)d_in[9];
    const float* W_mlp0       = (const float*)d_in[10];
    const float* W_mlp1       = (const float*)d_in[11];
    const float* W_mlp2       = (const float*)d_in[12];
    const float* W_down_s     = (const float*)d_in[13];
    const float* W_down_v     = (const float*)d_in[14];
    float* out = (float*)d_out;

    const int UP_SMEM    = (8192 + 8 * 256) * 4;            // 40 KB
    const int SKIP_SMEM  = (49152 + 8 * 256) * 4;           // 200 KB
    const int EDGE_SMEM  = 26848 * 4;                       // ~105 KB -> 2 blocks/SM
    const int FINAL_SMEM = (24576 + 8 * 520) * 4;           // ~114.5 KB

    cudaFuncSetAttribute(k_skip,  cudaFuncAttributeMaxDynamicSharedMemorySize, SKIP_SMEM);
    cudaFuncSetAttribute(k_edge,  cudaFuncAttributeMaxDynamicSharedMemorySize, EDGE_SMEM);
    cudaFuncSetAttribute(k_final, cudaFuncAttributeMaxDynamicSharedMemorySize, FINAL_SMEM);

    k_zero<<<2048, 256>>>();
    k_up<<<512, 256, UP_SMEM>>>(node_scalars, node_vectors, W_up_s, W_up_v);
    k_skip<<<296, 256, SKIP_SMEM>>>(node_scalars, node_vectors, node_specie, W_skip_s, W_skip_v);
    k_edge<<<296, 256, EDGE_SMEM>>>(vectors, senders, receivers, W_mlp0, W_mlp1, W_mlp2);
    k_final<<<296, 256, FINAL_SMEM>>>(W_down_s, W_down_v, out);
}

// round 8
// speedup vs baseline: 1.5169x; 1.5169x over previous
#include <cuda_runtime.h>
#include <math.h>

// Problem constants (fixed shapes)
#define NN 20000
#define EE 320000
#define CC 64

// ---------------- scratch (device globals; no allocation allowed) ----------------
__device__ __align__(16) float g_s[NN * CC];            // up-projected scalars  s[n][c]
__device__ __align__(16) float g_v[NN * CC * 3];        // up-projected vectors  v[n][c][m]
__device__ __align__(16) float g_skip_s[NN * 2 * CC];   // skip_s[n][o]
__device__ __align__(16) float g_skip_v[NN * CC * 3];   // skip_v[n][o][m]
__device__ __align__(16) float g_agg_s[NN * 2 * CC];    // agg_s raw sums
__device__ __align__(16) float g_agg_v[NN * 3 * 2 * CC];// agg_v[n][m][c2] raw sums
__device__ __align__(16) float g_mix[EE * 256];         // per-edge MLP output
__device__ __align__(16) float g_y[EE * 4];             // per-edge sqrt(3)*vhat (w=0)

__device__ __forceinline__ float swishf(float x) { return x / (1.0f + __expf(-x)); }

__device__ __forceinline__ void red4(float* p, float a, float b, float c, float d) {
    asm volatile("red.global.add.v4.f32 [%0], {%1,%2,%3,%4};"
                 :: "l"(p), "f"(a), "f"(b), "f"(c), "f"(d) : "memory");
}

// ---------------- kernel: zero aggregation buffers ----------------
__global__ void k_zero() {
    float4 z = make_float4(0.f, 0.f, 0.f, 0.f);
    int n1 = NN * 2 * CC / 4;
    for (int i = blockIdx.x * blockDim.x + threadIdx.x; i < n1; i += gridDim.x * blockDim.x)
        reinterpret_cast<float4*>(g_agg_s)[i] = z;
    int n2 = NN * 6 * CC / 4;
    for (int i = blockIdx.x * blockDim.x + threadIdx.x; i < n2; i += gridDim.x * blockDim.x)
        reinterpret_cast<float4*>(g_agg_v)[i] = z;
}

// ---------------- kernel: node up-projection ----------------
__global__ void __launch_bounds__(256) k_up(const float* __restrict__ scal,
                                            const float* __restrict__ nvec,
                                            const float* __restrict__ Wus,
                                            const float* __restrict__ Wuv) {
    extern __shared__ float sm[];
    float* sWs = sm;          // 64*64
    float* sWv = sm + 4096;   // 64*64
    float* sBuf = sm + 8192;  // 8 warps * 256
    int tid = threadIdx.x, wid = tid >> 5, l = tid & 31;
    for (int i = tid; i < 4096; i += 256) { sWs[i] = Wus[i]; sWv[i] = Wuv[i]; }
    __syncthreads();
    float* sc = sBuf + wid * 256;
    float* vb = sc + 64;
    int nwarp = gridDim.x * 8;
    for (int n = blockIdx.x * 8 + wid; n < NN; n += nwarp) {
        sc[l] = scal[n * 64 + l];
        sc[l + 32] = scal[n * 64 + l + 32];
#pragma unroll
        for (int q = 0; q < 6; q++) vb[l + q * 32] = nvec[n * 192 + l + q * 32];
        __syncwarp();
        float a0 = 0.f, a1 = 0.f;
#pragma unroll
        for (int k = 0; k < 64; k++) {
            float a = sc[k];
            a0 = fmaf(a, sWs[k * 64 + l], a0);
            a1 = fmaf(a, sWs[k * 64 + l + 32], a1);
        }
        g_s[n * 64 + l] = a0;
        g_s[n * 64 + l + 32] = a1;
        float v0[3] = {0.f, 0.f, 0.f}, v1[3] = {0.f, 0.f, 0.f};
#pragma unroll
        for (int k = 0; k < 64; k++) {
            float w0 = sWv[k * 64 + l], w1 = sWv[k * 64 + l + 32];
#pragma unroll
            for (int m = 0; m < 3; m++) {
                float a = vb[k * 3 + m];
                v0[m] = fmaf(a, w0, v0[m]);
                v1[m] = fmaf(a, w1, v1[m]);
            }
        }
#pragma unroll
        for (int m = 0; m < 3; m++) {
            g_v[n * 192 + l * 3 + m] = v0[m];
            g_v[n * 192 + (l + 32) * 3 + m] = v1[m];
        }
        __syncwarp();
    }
}

// ---------------- kernel: per-species skip projections ----------------
__global__ void __launch_bounds__(256) k_skip(const float* __restrict__ scal,
                                              const float* __restrict__ nvec,
                                              const int* __restrict__ specie,
                                              const float* __restrict__ Wss,
                                              const float* __restrict__ Wsv) {
    extern __shared__ float sm[];
    float* sS = sm;            // 32768
    float* sV = sm + 32768;    // 16384
    float* sBuf = sm + 49152;  // 8 * 256
    int tid = threadIdx.x, wid = tid >> 5, l = tid & 31;
    for (int i = tid; i < 32768; i += 256) sS[i] = Wss[i];
    for (int i = tid; i < 16384; i += 256) sV[i] = Wsv[i];
    __syncthreads();
    float* sc = sBuf + wid * 256;
    float* vb = sc + 64;
    int nwarp = gridDim.x * 8;
    for (int n = blockIdx.x * 8 + wid; n < NN; n += nwarp) {
        sc[l] = scal[n * 64 + l];
        sc[l + 32] = scal[n * 64 + l + 32];
#pragma unroll
        for (int q = 0; q < 6; q++) vb[l + q * 32] = nvec[n * 192 + l + q * 32];
        __syncwarp();
        int sp = specie[n];
        const float* ws = sS + sp * 8192;
        const float* wv = sV + sp * 4096;
        float a0 = 0.f, a1 = 0.f, a2 = 0.f, a3 = 0.f;
#pragma unroll
        for (int k = 0; k < 64; k++) {
            float x = sc[k];
            const float* w = ws + k * 128;
            a0 = fmaf(x, w[l], a0);
            a1 = fmaf(x, w[l + 32], a1);
            a2 = fmaf(x, w[l + 64], a2);
            a3 = fmaf(x, w[l + 96], a3);
        }
        g_skip_s[n * 128 + l] = a0;
        g_skip_s[n * 128 + l + 32] = a1;
        g_skip_s[n * 128 + l + 64] = a2;
        g_skip_s[n * 128 + l + 96] = a3;
        float v0[3] = {0.f, 0.f, 0.f}, v1[3] = {0.f, 0.f, 0.f};
#pragma unroll
        for (int k = 0; k < 64; k++) {
            float w0 = wv[k * 64 + l], w1 = wv[k * 64 + l + 32];
#pragma unroll
            for (int m = 0; m < 3; m++) {
                float a = vb[k * 3 + m];
                v0[m] = fmaf(a, w0, v0[m]);
                v1[m] = fmaf(a, w1, v1[m]);
            }
        }
#pragma unroll
        for (int m = 0; m < 3; m++) {
            g_skip_v[n * 192 + l * 3 + m] = v0[m];
            g_skip_v[n * 192 + (l + 32) * 3 + m] = v1[m];
        }
        __syncwarp();
    }
}

// ---------------- kernel: edge MLP (R4 phases 1-4) -> g_mix, g_y ----------------
// 64-edge tiles, 256 threads, 2 blocks/SM, [e][k] scalar-LDS layout (proven).
__global__ void __launch_bounds__(256, 2) k_mlp(const float* __restrict__ vectors,
                                                const float* __restrict__ W0,
                                                const float* __restrict__ W1,
                                                const float* __restrict__ W2) {
    extern __shared__ float sm[];
    float* sW0 = sm;                 // 512
    float* sW1 = sm + 512;           // 4096
    float* sW2 = sm + 4608;          // 16384
    float* sH  = sm + 20992;         // 64*65 = 4160, reused H0->H1
    float* sF  = sm + 25152;         // 64*9  = 576  -> total 25728 floats = 102912 B

    int tid = threadIdx.x;
    for (int i = tid; i < 512; i += 256) sW0[i] = W0[i];
    for (int i = tid; i < 4096; i += 256) sW1[i] = W1[i];
    for (int i = tid; i < 16384; i += 256) sW2[i] = W2[i];
    __syncthreads();

    const int og = tid >> 3;  // 0..31
    const int eg = tid & 7;   // 0..7
    const float SQRT2 = 1.41421356237309515f;
    const float SQRT3 = 1.73205080756887729f;
    const float PI = 3.14159265358979323846f;

    int ntile = EE / 64;
    for (int t = blockIdx.x; t < ntile; t += gridDim.x) {
        int e0 = t * 64;
        // ---- phase 1: per-edge features (threads 0..63) ----
        if (tid < 64) {
            int e = e0 + tid;
            float vx = vectors[e * 3 + 0];
            float vy = vectors[e * 3 + 1];
            float vz = vectors[e * 3 + 2];
            float x = sqrtf(vx * vx + vy * vy + vz * vz);
            float sx = (x == 0.f) ? 1.f : x;
            float inv = 1.f / sx;
            float4 yv = make_float4(SQRT3 * vx * inv, SQRT3 * vy * inv, SQRT3 * vz * inv, 0.f);
            *reinterpret_cast<float4*>(g_y + e * 4) = yv;
            float u = fminf(x, 1.f);
            float u2 = u * u, u3 = u2 * u, u6 = u3 * u3, u7 = u6 * u, u8 = u7 * u;
            float env = (x < 1.f) ? (1.f - 28.f * u6 + 48.f * u7 - 21.f * u8) : 0.f;
            float s1, c1;
            sincosf(PI * x, &s1, &c1);
            float pref = SQRT2 * inv * env;
            float sn = s1, cn = c1;
            sF[tid * 9 + 0] = pref * sn;
#pragma unroll
            for (int b = 1; b < 8; b++) {
                float sn1 = sn * c1 + cn * s1;
                float cn1 = cn * c1 - sn * s1;
                sn = sn1; cn = cn1;
                sF[tid * 9 + b] = pref * sn;
            }
        }
        __syncthreads();

        // ---- phase 2: h0 = swish(feat @ W0) ----
        {
            float a0[8], a1[8];
#pragma unroll
            for (int i = 0; i < 8; i++) { a0[i] = 0.f; a1[i] = 0.f; }
#pragma unroll
            for (int b = 0; b < 8; b++) {
                float w0 = sW0[b * 64 + og];
                float w1 = sW0[b * 64 + og + 32];
#pragma unroll
                for (int i = 0; i < 8; i++) {
                    float f = sF[(eg * 8 + i) * 9 + b];
                    a0[i] = fmaf(f, w0, a0[i]);
                    a1[i] = fmaf(f, w1, a1[i]);
                }
            }
#pragma unroll
            for (int i = 0; i < 8; i++) {
                sH[(eg * 8 + i) * 65 + og] = swishf(a0[i]);
                sH[(eg * 8 + i) * 65 + og + 32] = swishf(a1[i]);
            }
        }
        __syncthreads();

        // ---- phase 3: h1 = swish(h0 @ W1), in place ----
        {
            float a0[8], a1[8];
#pragma unroll
            for (int i = 0; i < 8; i++) { a0[i] = 0.f; a1[i] = 0.f; }
#pragma unroll 2
            for (int k = 0; k < 64; k++) {
                float w0 = sW1[k * 64 + og];
                float w1 = sW1[k * 64 + og + 32];
#pragma unroll
                for (int i = 0; i < 8; i++) {
                    float h = sH[(eg * 8 + i) * 65 + k];
                    a0[i] = fmaf(h, w0, a0[i]);
                    a1[i] = fmaf(h, w1, a1[i]);
                }
            }
            __syncthreads();
#pragma unroll
            for (int i = 0; i < 8; i++) {
                sH[(eg * 8 + i) * 65 + og] = swishf(a0[i]);
                sH[(eg * 8 + i) * 65 + og + 32] = swishf(a1[i]);
            }
        }
        __syncthreads();

        // ---- phase 4: mix = h1 @ W2, thread tile 8e x 8j ----
        float acc[8][8];
#pragma unroll
        for (int i = 0; i < 8; i++)
#pragma unroll
            for (int q = 0; q < 8; q++) acc[i][q] = 0.f;
        {
            const int j0 = og * 8;
#pragma unroll 2
            for (int k = 0; k < 64; k++) {
                float4 b0 = *reinterpret_cast<const float4*>(sW2 + k * 256 + j0);
                float4 b1 = *reinterpret_cast<const float4*>(sW2 + k * 256 + j0 + 4);
#pragma unroll
                for (int i = 0; i < 8; i++) {
                    float a = sH[(eg * 8 + i) * 65 + k];
                    acc[i][0] = fmaf(a, b0.x, acc[i][0]);
                    acc[i][1] = fmaf(a, b0.y, acc[i][1]);
                    acc[i][2] = fmaf(a, b0.z, acc[i][2]);
                    acc[i][3] = fmaf(a, b0.w, acc[i][3]);
                    acc[i][4] = fmaf(a, b1.x, acc[i][4]);
                    acc[i][5] = fmaf(a, b1.y, acc[i][5]);
                    acc[i][6] = fmaf(a, b1.z, acc[i][6]);
                    acc[i][7] = fmaf(a, b1.w, acc[i][7]);
                }
            }
        }

        // ---- phase 5': store mix coalesced ----
        {
            const int j0 = og * 8;
#pragma unroll
            for (int i = 0; i < 8; i++) {
                int e = e0 + eg * 8 + i;
                *reinterpret_cast<float4*>(g_mix + e * 256 + j0) =
                    make_float4(acc[i][0], acc[i][1], acc[i][2], acc[i][3]);
                *reinterpret_cast<float4*>(g_mix + e * 256 + j0 + 4) =
                    make_float4(acc[i][4], acc[i][5], acc[i][6], acc[i][7]);
            }
        }
        __syncthreads();  // protect sF/sH before next tile
    }
}

// ---------------- kernel: gather + message + coalesced scatter ----------------
// 256 threads = 2 edges x 128 threads. Stage s/v/mix/Y in smem (coalesced LDG),
// then each thread emits ONE red.v4 with warp-contiguous targets.
__global__ void __launch_bounds__(256) k_scatter(const int* __restrict__ senders,
                                                 const int* __restrict__ receivers) {
    __shared__ float sb[2][520];  // per half: S[64] V[192] M[256] Y[4] (+pad)
    int tid = threadIdx.x;
    int h = tid >> 7, l = tid & 127;
    const float INV_SQRT3 = 0.57735026918962576f;
    float* S = sb[h];
    float* V = S + 64;
    float* M = V + 192;
    float* Yp = M + 256;
    int npair = EE / 2;
    for (int p = blockIdx.x; p < npair; p += gridDim.x) {
        int e = p * 2 + h;
        int snd = senders[e];
        if (l < 64) {
            *reinterpret_cast<float4*>(M + l * 4) =
                *reinterpret_cast<const float4*>(g_mix + e * 256 + l * 4);
        } else if (l < 112) {
            int idx = l - 64;
            *reinterpret_cast<float4*>(V + idx * 4) =
                *reinterpret_cast<const float4*>(g_v + snd * 192 + idx * 4);
        } else {
            int idx = l - 112;
            *reinterpret_cast<float4*>(S + idx * 4) =
                *reinterpret_cast<const float4*>(g_s + snd * 64 + idx * 4);
        }
        if (l == 0)
            *reinterpret_cast<float4*>(Yp) = *reinterpret_cast<const float4*>(g_y + e * 4);
        __syncthreads();

        int rcv = receivers[e];
        if (l < 16) {
            int c = l * 4;
            red4(g_agg_s + rcv * 128 + c,
                 S[c] * M[c], S[c + 1] * M[c + 1], S[c + 2] * M[c + 2], S[c + 3] * M[c + 3]);
        } else if (l < 32) {
            int c = (l - 16) * 4;
            float y0 = Yp[0], y1 = Yp[1], y2 = Yp[2];
            float v[4];
#pragma unroll
            for (int t = 0; t < 4; t++) {
                int cc = c + t;
                v[t] = (V[cc * 3] * y0 + V[cc * 3 + 1] * y1 + V[cc * 3 + 2] * y2)
                       * INV_SQRT3 * M[64 + cc];
            }
            red4(g_agg_s + rcv * 128 + 64 + c, v[0], v[1], v[2], v[3]);
        } else {
            int q = l - 32;           // 0..95
            int m = q >> 5, cb = q & 31;
            int c2 = cb * 4;
            float v[4];
            if (c2 < 64) {
#pragma unroll
                for (int t = 0; t < 4; t++)
                    v[t] = V[(c2 + t) * 3 + m] * M[128 + c2 + t];
            } else {
                int c = c2 - 64;
                float ym = Yp[m];
#pragma unroll
                for (int t = 0; t < 4; t++)
                    v[t] = S[c + t] * ym * M[192 + c + t];
            }
            red4(g_agg_v + rcv * 384 + m * 128 + c2, v[0], v[1], v[2], v[3]);
        }
        __syncthreads();  // protect staging before next iter
    }
}

// ---------------- kernel: final down-projection + skip + gating + output ----------------
__global__ void __launch_bounds__(256) k_final(const float* __restrict__ Wds,
                                               const float* __restrict__ Wdv,
                                               float* __restrict__ out) {
    extern __shared__ float sm[];
    float* sWs = sm;            // 16384
    float* sWv = sm + 16384;    // 8192
    float* sBuf = sm + 24576;   // 8 * 520
    int tid = threadIdx.x, wid = tid >> 5, l = tid & 31;
    for (int i = tid; i < 16384; i += 256) sWs[i] = Wds[i];
    for (int i = tid; i < 8192; i += 256) sWv[i] = Wdv[i];
    __syncthreads();
    float* As = sBuf + wid * 520;
    float* Av = As + 128;
    const float INV = 0.25f;
    int nwarp = gridDim.x * 8;
    for (int n = blockIdx.x * 8 + wid; n < NN; n += nwarp) {
#pragma unroll
        for (int q = 0; q < 4; q++) As[l + 32 * q] = g_agg_s[n * 128 + l + 32 * q];
#pragma unroll
        for (int q = 0; q < 12; q++) Av[l + 32 * q] = g_agg_v[n * 384 + l + 32 * q];
        __syncwarp();
        float a0 = 0.f, a1 = 0.f, a2 = 0.f, a3 = 0.f;
#pragma unroll 4
        for (int k = 0; k < 128; k++) {
            float x = As[k];
            const float* w = sWs + k * 128;
            a0 = fmaf(x, w[l], a0);
            a1 = fmaf(x, w[l + 32], a1);
            a2 = fmaf(x, w[l + 64], a2);
            a3 = fmaf(x, w[l + 96], a3);
        }
        float os0 = INV * a0 + g_skip_s[n * 128 + l];
        float os1 = INV * a1 + g_skip_s[n * 128 + l + 32];
        float os2 = INV * a2 + g_skip_s[n * 128 + l + 64];
        float os3 = INV * a3 + g_skip_s[n * 128 + l + 96];
        float scal0 = swishf(os0), scal1 = swishf(os1);
        float gate0 = swishf(os2), gate1 = swishf(os3);
        float v0[3] = {0.f, 0.f, 0.f}, v1[3] = {0.f, 0.f, 0.f};
#pragma unroll 4
        for (int k = 0; k < 128; k++) {
            float w0 = sWv[k * 64 + l], w1 = sWv[k * 64 + l + 32];
#pragma unroll
            for (int m = 0; m < 3; m++) {
                float a = Av[m * 128 + k];
                v0[m] = fmaf(a, w0, v0[m]);
                v1[m] = fmaf(a, w1, v1[m]);
            }
        }
        out[n * 256 + l] = scal0;
        out[n * 256 + l + 32] = scal1;
#pragma unroll
        for (int m = 0; m < 3; m++) {
            float ov0 = INV * v0[m] + g_skip_v[n * 192 + l * 3 + m];
            float ov1 = INV * v1[m] + g_skip_v[n * 192 + (l + 32) * 3 + m];
            out[n * 256 + 64 + l * 3 + m] = ov0 * gate0;
            out[n * 256 + 64 + (l + 32) * 3 + m] = ov1 * gate1;
        }
        __syncwarp();
    }
}

// ---------------- launch ----------------
extern "C" void kernel_launch(void* const* d_in, const int* in_sizes, int n_in,
                              void* d_out, int out_size) {
    const float* vectors      = (const float*)d_in[0];
    const float* node_scalars = (const float*)d_in[1];
    const float* node_vectors = (const float*)d_in[2];
    const int*   node_specie  = (const int*)d_in[3];
    const int*   senders      = (const int*)d_in[4];
    const int*   receivers    = (const int*)d_in[5];
    const float* W_skip_s     = (const float*)d_in[6];
    const float* W_skip_v     = (const float*)d_in[7];
    const float* W_up_s       = (const float*)d_in[8];
    const float* W_up_v       = (const float*)d_in[9];
    const float* W_mlp0       = (const float*)d_in[10];
    const float* W_mlp1       = (const float*)d_in[11];
    const float* W_mlp2       = (const float*)d_in[12];
    const float* W_down_s     = (const float*)d_in[13];
    const float* W_down_v     = (const float*)d_in[14];
    float* out = (float*)d_out;

    const int UP_SMEM    = (8192 + 8 * 256) * 4;            // 40 KB
    const int SKIP_SMEM  = (49152 + 8 * 256) * 4;           // 200 KB
    const int MLP_SMEM   = 25728 * 4;                       // ~100.5 KB -> 2 blocks/SM
    const int FINAL_SMEM = (24576 + 8 * 520) * 4;           // ~114.5 KB

    cudaFuncSetAttribute(k_skip,  cudaFuncAttributeMaxDynamicSharedMemorySize, SKIP_SMEM);
    cudaFuncSetAttribute(k_mlp,   cudaFuncAttributeMaxDynamicSharedMemorySize, MLP_SMEM);
    cudaFuncSetAttribute(k_final, cudaFuncAttributeMaxDynamicSharedMemorySize, FINAL_SMEM);

    k_zero<<<2048, 256>>>();
    k_up<<<512, 256, UP_SMEM>>>(node_scalars, node_vectors, W_up_s, W_up_v);
    k_skip<<<296, 256, SKIP_SMEM>>>(node_scalars, node_vectors, node_specie, W_skip_s, W_skip_v);
    k_mlp<<<296, 256, MLP_SMEM>>>(vectors, W_mlp0, W_mlp1, W_mlp2);
    k_scatter<<<2960, 256>>>(senders, receivers);
    k_final<<<296, 256, FINAL_SMEM>>>(W_down_s, W_down_v, out);
}

// round 9
// speedup vs baseline: 1.6303x; 1.0748x over previous
#include <cuda_runtime.h>
#include <math.h>

// Problem constants (fixed shapes)
#define NN 20000
#define EE 320000
#define CC 64

// ---------------- scratch (device globals; no allocation allowed) ----------------
__device__ __align__(16) float g_s[NN * CC];            // up-projected scalars  s[n][c]
__device__ __align__(16) float g_v[NN * CC * 3];        // up-projected vectors  v[n][c][m]
__device__ __align__(16) float g_skip_s[NN * 2 * CC];   // skip_s[n][o]
__device__ __align__(16) float g_skip_v[NN * CC * 3];   // skip_v[n][o][m]
__device__ __align__(16) float g_agg_s[NN * 2 * CC];    // agg_s raw sums
__device__ __align__(16) float g_agg_v[NN * 3 * 2 * CC];// agg_v[n][m][c2] raw sums
__device__ __align__(16) float g_mix[EE * 256];         // per-edge MLP output
__device__ __align__(16) float g_y[EE * 4];             // per-edge sqrt(3)*vhat (w=0)

__device__ __forceinline__ float swishf(float x) { return x / (1.0f + __expf(-x)); }

__device__ __forceinline__ void red4(float* p, float a, float b, float c, float d) {
    asm volatile("red.global.add.v4.f32 [%0], {%1,%2,%3,%4};"
                 :: "l"(p), "f"(a), "f"(b), "f"(c), "f"(d) : "memory");
}

// ---------------- kernel: zero aggregation buffers ----------------
__global__ void k_zero() {
    float4 z = make_float4(0.f, 0.f, 0.f, 0.f);
    int n1 = NN * 2 * CC / 4;
    for (int i = blockIdx.x * blockDim.x + threadIdx.x; i < n1; i += gridDim.x * blockDim.x)
        reinterpret_cast<float4*>(g_agg_s)[i] = z;
    int n2 = NN * 6 * CC / 4;
    for (int i = blockIdx.x * blockDim.x + threadIdx.x; i < n2; i += gridDim.x * blockDim.x)
        reinterpret_cast<float4*>(g_agg_v)[i] = z;
}

// ---------------- kernel: node up-projection ----------------
__global__ void __launch_bounds__(256) k_up(const float* __restrict__ scal,
                                            const float* __restrict__ nvec,
                                            const float* __restrict__ Wus,
                                            const float* __restrict__ Wuv) {
    extern __shared__ float sm[];
    float* sWs = sm;          // 64*64
    float* sWv = sm + 4096;   // 64*64
    float* sBuf = sm + 8192;  // 8 warps * 256
    int tid = threadIdx.x, wid = tid >> 5, l = tid & 31;
    for (int i = tid; i < 4096; i += 256) { sWs[i] = Wus[i]; sWv[i] = Wuv[i]; }
    __syncthreads();
    float* sc = sBuf + wid * 256;
    float* vb = sc + 64;
    int nwarp = gridDim.x * 8;
    for (int n = blockIdx.x * 8 + wid; n < NN; n += nwarp) {
        sc[l] = scal[n * 64 + l];
        sc[l + 32] = scal[n * 64 + l + 32];
#pragma unroll
        for (int q = 0; q < 6; q++) vb[l + q * 32] = nvec[n * 192 + l + q * 32];
        __syncwarp();
        float a0 = 0.f, a1 = 0.f;
#pragma unroll
        for (int k = 0; k < 64; k++) {
            float a = sc[k];
            a0 = fmaf(a, sWs[k * 64 + l], a0);
            a1 = fmaf(a, sWs[k * 64 + l + 32], a1);
        }
        g_s[n * 64 + l] = a0;
        g_s[n * 64 + l + 32] = a1;
        float v0[3] = {0.f, 0.f, 0.f}, v1[3] = {0.f, 0.f, 0.f};
#pragma unroll
        for (int k = 0; k < 64; k++) {
            float w0 = sWv[k * 64 + l], w1 = sWv[k * 64 + l + 32];
#pragma unroll
            for (int m = 0; m < 3; m++) {
                float a = vb[k * 3 + m];
                v0[m] = fmaf(a, w0, v0[m]);
                v1[m] = fmaf(a, w1, v1[m]);
            }
        }
#pragma unroll
        for (int m = 0; m < 3; m++) {
            g_v[n * 192 + l * 3 + m] = v0[m];
            g_v[n * 192 + (l + 32) * 3 + m] = v1[m];
        }
        __syncwarp();
    }
}

// ---------------- kernel: per-species skip projections ----------------
__global__ void __launch_bounds__(256) k_skip(const float* __restrict__ scal,
                                              const float* __restrict__ nvec,
                                              const int* __restrict__ specie,
                                              const float* __restrict__ Wss,
                                              const float* __restrict__ Wsv) {
    extern __shared__ float sm[];
    float* sS = sm;            // 32768
    float* sV = sm + 32768;    // 16384
    float* sBuf = sm + 49152;  // 8 * 256
    int tid = threadIdx.x, wid = tid >> 5, l = tid & 31;
    for (int i = tid; i < 32768; i += 256) sS[i] = Wss[i];
    for (int i = tid; i < 16384; i += 256) sV[i] = Wsv[i];
    __syncthreads();
    float* sc = sBuf + wid * 256;
    float* vb = sc + 64;
    int nwarp = gridDim.x * 8;
    for (int n = blockIdx.x * 8 + wid; n < NN; n += nwarp) {
        sc[l] = scal[n * 64 + l];
        sc[l + 32] = scal[n * 64 + l + 32];
#pragma unroll
        for (int q = 0; q < 6; q++) vb[l + q * 32] = nvec[n * 192 + l + q * 32];
        __syncwarp();
        int sp = specie[n];
        const float* ws = sS + sp * 8192;
        const float* wv = sV + sp * 4096;
        float a0 = 0.f, a1 = 0.f, a2 = 0.f, a3 = 0.f;
#pragma unroll
        for (int k = 0; k < 64; k++) {
            float x = sc[k];
            const float* w = ws + k * 128;
            a0 = fmaf(x, w[l], a0);
            a1 = fmaf(x, w[l + 32], a1);
            a2 = fmaf(x, w[l + 64], a2);
            a3 = fmaf(x, w[l + 96], a3);
        }
        g_skip_s[n * 128 + l] = a0;
        g_skip_s[n * 128 + l + 32] = a1;
        g_skip_s[n * 128 + l + 64] = a2;
        g_skip_s[n * 128 + l + 96] = a3;
        float v0[3] = {0.f, 0.f, 0.f}, v1[3] = {0.f, 0.f, 0.f};
#pragma unroll
        for (int k = 0; k < 64; k++) {
            float w0 = wv[k * 64 + l], w1 = wv[k * 64 + l + 32];
#pragma unroll
            for (int m = 0; m < 3; m++) {
                float a = vb[k * 3 + m];
                v0[m] = fmaf(a, w0, v0[m]);
                v1[m] = fmaf(a, w1, v1[m]);
            }
        }
#pragma unroll
        for (int m = 0; m < 3; m++) {
            g_skip_v[n * 192 + l * 3 + m] = v0[m];
            g_skip_v[n * 192 + (l + 32) * 3 + m] = v1[m];
        }
        __syncwarp();
    }
}

// ---------------- kernel: edge MLP -> g_mix, g_y ----------------
// 64-edge tiles, 256 threads, 2 blocks/SM. Edge ownership remapped to
// e = eg + 8*i so per-(i,k) warp LDS addresses step by 65 floats -> banks
// step by 1 across eg -> conflict-free broadcast (1 wavefront per a-load,
// was 2). No other change vs the R8 kernel.
__global__ void __launch_bounds__(256, 2) k_mlp(const float* __restrict__ vectors,
                                                const float* __restrict__ W0,
                                                const float* __restrict__ W1,
                                                const float* __restrict__ W2) {
    extern __shared__ float sm[];
    float* sW0 = sm;                 // 512
    float* sW1 = sm + 512;           // 4096
    float* sW2 = sm + 4608;          // 16384
    float* sH  = sm + 20992;         // 64*65 = 4160, reused H0->H1
    float* sF  = sm + 25152;         // 64*9  = 576  -> total 25728 floats = 102912 B

    int tid = threadIdx.x;
    for (int i = tid; i < 512; i += 256) sW0[i] = W0[i];
    for (int i = tid; i < 4096; i += 256) sW1[i] = W1[i];
    for (int i = tid; i < 16384; i += 256) sW2[i] = W2[i];
    __syncthreads();

    const int og = tid >> 3;  // 0..31
    const int eg = tid & 7;   // 0..7
    const float SQRT2 = 1.41421356237309515f;
    const float SQRT3 = 1.73205080756887729f;
    const float PI = 3.14159265358979323846f;

    int ntile = EE / 64;
    for (int t = blockIdx.x; t < ntile; t += gridDim.x) {
        int e0 = t * 64;
        // ---- phase 1: per-edge features (threads 0..63) ----
        if (tid < 64) {
            int e = e0 + tid;
            float vx = vectors[e * 3 + 0];
            float vy = vectors[e * 3 + 1];
            float vz = vectors[e * 3 + 2];
            float x = sqrtf(vx * vx + vy * vy + vz * vz);
            float sx = (x == 0.f) ? 1.f : x;
            float inv = 1.f / sx;
            float4 yv = make_float4(SQRT3 * vx * inv, SQRT3 * vy * inv, SQRT3 * vz * inv, 0.f);
            *reinterpret_cast<float4*>(g_y + e * 4) = yv;
            float u = fminf(x, 1.f);
            float u2 = u * u, u3 = u2 * u, u6 = u3 * u3, u7 = u6 * u, u8 = u7 * u;
            float env = (x < 1.f) ? (1.f - 28.f * u6 + 48.f * u7 - 21.f * u8) : 0.f;
            float s1, c1;
            sincosf(PI * x, &s1, &c1);
            float pref = SQRT2 * inv * env;
            float sn = s1, cn = c1;
            sF[tid * 9 + 0] = pref * sn;
#pragma unroll
            for (int b = 1; b < 8; b++) {
                float sn1 = sn * c1 + cn * s1;
                float cn1 = cn * c1 - sn * s1;
                sn = sn1; cn = cn1;
                sF[tid * 9 + b] = pref * sn;
            }
        }
        __syncthreads();

        // ---- phase 2: h0 = swish(feat @ W0) ----
        {
            float a0[8], a1[8];
#pragma unroll
            for (int i = 0; i < 8; i++) { a0[i] = 0.f; a1[i] = 0.f; }
#pragma unroll
            for (int b = 0; b < 8; b++) {
                float w0 = sW0[b * 64 + og];
                float w1 = sW0[b * 64 + og + 32];
#pragma unroll
                for (int i = 0; i < 8; i++) {
                    float f = sF[(eg + 8 * i) * 9 + b];
                    a0[i] = fmaf(f, w0, a0[i]);
                    a1[i] = fmaf(f, w1, a1[i]);
                }
            }
#pragma unroll
            for (int i = 0; i < 8; i++) {
                sH[(eg + 8 * i) * 65 + og] = swishf(a0[i]);
                sH[(eg + 8 * i) * 65 + og + 32] = swishf(a1[i]);
            }
        }
        __syncthreads();

        // ---- phase 3: h1 = swish(h0 @ W1), in place ----
        {
            float a0[8], a1[8];
#pragma unroll
            for (int i = 0; i < 8; i++) { a0[i] = 0.f; a1[i] = 0.f; }
#pragma unroll 2
            for (int k = 0; k < 64; k++) {
                float w0 = sW1[k * 64 + og];
                float w1 = sW1[k * 64 + og + 32];
#pragma unroll
                for (int i = 0; i < 8; i++) {
                    float h = sH[(eg + 8 * i) * 65 + k];
                    a0[i] = fmaf(h, w0, a0[i]);
                    a1[i] = fmaf(h, w1, a1[i]);
                }
            }
            __syncthreads();
#pragma unroll
            for (int i = 0; i < 8; i++) {
                sH[(eg + 8 * i) * 65 + og] = swishf(a0[i]);
                sH[(eg + 8 * i) * 65 + og + 32] = swishf(a1[i]);
            }
        }
        __syncthreads();

        // ---- phase 4: mix = h1 @ W2, thread tile 8e x 8j ----
        float acc[8][8];
#pragma unroll
        for (int i = 0; i < 8; i++)
#pragma unroll
            for (int q = 0; q < 8; q++) acc[i][q] = 0.f;
        {
            const int j0 = og * 8;
#pragma unroll 2
            for (int k = 0; k < 64; k++) {
                float4 b0 = *reinterpret_cast<const float4*>(sW2 + k * 256 + j0);
                float4 b1 = *reinterpret_cast<const float4*>(sW2 + k * 256 + j0 + 4);
#pragma unroll
                for (int i = 0; i < 8; i++) {
                    float a = sH[(eg + 8 * i) * 65 + k];
                    acc[i][0] = fmaf(a, b0.x, acc[i][0]);
                    acc[i][1] = fmaf(a, b0.y, acc[i][1]);
                    acc[i][2] = fmaf(a, b0.z, acc[i][2]);
                    acc[i][3] = fmaf(a, b0.w, acc[i][3]);
                    acc[i][4] = fmaf(a, b1.x, acc[i][4]);
                    acc[i][5] = fmaf(a, b1.y, acc[i][5]);
                    acc[i][6] = fmaf(a, b1.z, acc[i][6]);
                    acc[i][7] = fmaf(a, b1.w, acc[i][7]);
                }
            }
        }

        // ---- phase 5': store mix coalesced ----
        {
            const int j0 = og * 8;
#pragma unroll
            for (int i = 0; i < 8; i++) {
                int e = e0 + eg + 8 * i;
                *reinterpret_cast<float4*>(g_mix + e * 256 + j0) =
                    make_float4(acc[i][0], acc[i][1], acc[i][2], acc[i][3]);
                *reinterpret_cast<float4*>(g_mix + e * 256 + j0 + 4) =
                    make_float4(acc[i][4], acc[i][5], acc[i][6], acc[i][7]);
            }
        }
        __syncthreads();  // protect sF/sH before next tile
    }
}

// ---------------- kernel: gather + message + coalesced scatter ----------------
__global__ void __launch_bounds__(256) k_scatter(const int* __restrict__ senders,
                                                 const int* __restrict__ receivers) {
    __shared__ float sb[2][520];  // per half: S[64] V[192] M[256] Y[4] (+pad)
    int tid = threadIdx.x;
    int h = tid >> 7, l = tid & 127;
    const float INV_SQRT3 = 0.57735026918962576f;
    float* S = sb[h];
    float* V = S + 64;
    float* M = V + 192;
    float* Yp = M + 256;
    int npair = EE / 2;
    for (int p = blockIdx.x; p < npair; p += gridDim.x) {
        int e = p * 2 + h;
        int snd = senders[e];
        if (l < 64) {
            *reinterpret_cast<float4*>(M + l * 4) =
                *reinterpret_cast<const float4*>(g_mix + e * 256 + l * 4);
        } else if (l < 112) {
            int idx = l - 64;
            *reinterpret_cast<float4*>(V + idx * 4) =
                *reinterpret_cast<const float4*>(g_v + snd * 192 + idx * 4);
        } else {
            int idx = l - 112;
            *reinterpret_cast<float4*>(S + idx * 4) =
                *reinterpret_cast<const float4*>(g_s + snd * 64 + idx * 4);
        }
        if (l == 0)
            *reinterpret_cast<float4*>(Yp) = *reinterpret_cast<const float4*>(g_y + e * 4);
        __syncthreads();

        int rcv = receivers[e];
        if (l < 16) {
            int c = l * 4;
            red4(g_agg_s + rcv * 128 + c,
                 S[c] * M[c], S[c + 1] * M[c + 1], S[c + 2] * M[c + 2], S[c + 3] * M[c + 3]);
        } else if (l < 32) {
            int c = (l - 16) * 4;
            float y0 = Yp[0], y1 = Yp[1], y2 = Yp[2];
            float v[4];
#pragma unroll
            for (int t = 0; t < 4; t++) {
                int cc = c + t;
                v[t] = (V[cc * 3] * y0 + V[cc * 3 + 1] * y1 + V[cc * 3 + 2] * y2)
                       * INV_SQRT3 * M[64 + cc];
            }
            red4(g_agg_s + rcv * 128 + 64 + c, v[0], v[1], v[2], v[3]);
        } else {
            int q = l - 32;           // 0..95
            int m = q >> 5, cb = q & 31;
            int c2 = cb * 4;
            float v[4];
            if (c2 < 64) {
#pragma unroll
                for (int t = 0; t < 4; t++)
                    v[t] = V[(c2 + t) * 3 + m] * M[128 + c2 + t];
            } else {
                int c = c2 - 64;
                float ym = Yp[m];
#pragma unroll
                for (int t = 0; t < 4; t++)
                    v[t] = S[c + t] * ym * M[192 + c + t];
            }
            red4(g_agg_v + rcv * 384 + m * 128 + c2, v[0], v[1], v[2], v[3]);
        }
        __syncthreads();  // protect staging before next iter
    }
}

// ---------------- kernel: final down-projection + skip + gating + output ----------------
__global__ void __launch_bounds__(256) k_final(const float* __restrict__ Wds,
                                               const float* __restrict__ Wdv,
                                               float* __restrict__ out) {
    extern __shared__ float sm[];
    float* sWs = sm;            // 16384
    float* sWv = sm + 16384;    // 8192
    float* sBuf = sm + 24576;   // 8 * 520
    int tid = threadIdx.x, wid = tid >> 5, l = tid & 31;
    for (int i = tid; i < 16384; i += 256) sWs[i] = Wds[i];
    for (int i = tid; i < 8192; i += 256) sWv[i] = Wdv[i];
    __syncthreads();
    float* As = sBuf + wid * 520;
    float* Av = As + 128;
    const float INV = 0.25f;
    int nwarp = gridDim.x * 8;
    for (int n = blockIdx.x * 8 + wid; n < NN; n += nwarp) {
#pragma unroll
        for (int q = 0; q < 4; q++) As[l + 32 * q] = g_agg_s[n * 128 + l + 32 * q];
#pragma unroll
        for (int q = 0; q < 12; q++) Av[l + 32 * q] = g_agg_v[n * 384 + l + 32 * q];
        __syncwarp();
        float a0 = 0.f, a1 = 0.f, a2 = 0.f, a3 = 0.f;
#pragma unroll 4
        for (int k = 0; k < 128; k++) {
            float x = As[k];
            const float* w = sWs + k * 128;
            a0 = fmaf(x, w[l], a0);
            a1 = fmaf(x, w[l + 32], a1);
            a2 = fmaf(x, w[l + 64], a2);
            a3 = fmaf(x, w[l + 96], a3);
        }
        float os0 = INV * a0 + g_skip_s[n * 128 + l];
        float os1 = INV * a1 + g_skip_s[n * 128 + l + 32];
        float os2 = INV * a2 + g_skip_s[n * 128 + l + 64];
        float os3 = INV * a3 + g_skip_s[n * 128 + l + 96];
        float scal0 = swishf(os0), scal1 = swishf(os1);
        float gate0 = swishf(os2), gate1 = swishf(os3);
        float v0[3] = {0.f, 0.f, 0.f}, v1[3] = {0.f, 0.f, 0.f};
#pragma unroll 4
        for (int k = 0; k < 128; k++) {
            float w0 = sWv[k * 64 + l], w1 = sWv[k * 64 + l + 32];
#pragma unroll
            for (int m = 0; m < 3; m++) {
                float a = Av[m * 128 + k];
                v0[m] = fmaf(a, w0, v0[m]);
                v1[m] = fmaf(a, w1, v1[m]);
            }
        }
        out[n * 256 + l] = scal0;
        out[n * 256 + l + 32] = scal1;
#pragma unroll
        for (int m = 0; m < 3; m++) {
            float ov0 = INV * v0[m] + g_skip_v[n * 192 + l * 3 + m];
            float ov1 = INV * v1[m] + g_skip_v[n * 192 + (l + 32) * 3 + m];
            out[n * 256 + 64 + l * 3 + m] = ov0 * gate0;
            out[n * 256 + 64 + (l + 32) * 3 + m] = ov1 * gate1;
        }
        __syncwarp();
    }
}

// ---------------- launch ----------------
extern "C" void kernel_launch(void* const* d_in, const int* in_sizes, int n_in,
                              void* d_out, int out_size) {
    const float* vectors      = (const float*)d_in[0];
    const float* node_scalars = (const float*)d_in[1];
    const float* node_vectors = (const float*)d_in[2];
    const int*   node_specie  = (const int*)d_in[3];
    const int*   senders      = (const int*)d_in[4];
    const int*   receivers    = (const int*)d_in[5];
    const float* W_skip_s     = (const float*)d_in[6];
    const float* W_skip_v     = (const float*)d_in[7];
    const float* W_up_s       = (const float*)d_in[8];
    const float* W_up_v       = (const float*)d_in[9];
    const float* W_mlp0       = (const float*)d_in[10];
    const float* W_mlp1       = (const float*)d_in[11];
    const float* W_mlp2       = (const float*)d_in[12];
    const float* W_down_s     = (const float*)d_in[13];
    const float* W_down_v     = (const float*)d_in[14];
    float* out = (float*)d_out;

    const int UP_SMEM    = (8192 + 8 * 256) * 4;            // 40 KB
    const int SKIP_SMEM  = (49152 + 8 * 256) * 4;           // 200 KB
    const int MLP_SMEM   = 25728 * 4;                       // ~100.5 KB -> 2 blocks/SM
    const int FINAL_SMEM = (24576 + 8 * 520) * 4;           // ~114.5 KB

    cudaFuncSetAttribute(k_skip,  cudaFuncAttributeMaxDynamicSharedMemorySize, SKIP_SMEM);
    cudaFuncSetAttribute(k_mlp,   cudaFuncAttributeMaxDynamicSharedMemorySize, MLP_SMEM);
    cudaFuncSetAttribute(k_final, cudaFuncAttributeMaxDynamicSharedMemorySize, FINAL_SMEM);

    k_zero<<<2048, 256>>>();
    k_up<<<512, 256, UP_SMEM>>>(node_scalars, node_vectors, W_up_s, W_up_v);
    k_skip<<<296, 256, SKIP_SMEM>>>(node_scalars, node_vectors, node_specie, W_skip_s, W_skip_v);
    k_mlp<<<296, 256, MLP_SMEM>>>(vectors, W_mlp0, W_mlp1, W_mlp2);
    k_scatter<<<2960, 256>>>(senders, receivers);
    k_final<<<296, 256, FINAL_SMEM>>>(W_down_s, W_down_v, out);
}

// round 11
// speedup vs baseline: 1.7274x; 1.0596x over previous
#include <cuda_runtime.h>
#include <math.h>

// Problem constants (fixed shapes)
#define NN 20000
#define EE 320000
#define CC 64

// ---------------- scratch (device globals; no allocation allowed) ----------------
__device__ __align__(16) float g_s[NN * CC];            // up-projected scalars  s[n][c]
__device__ __align__(16) float g_v[NN * CC * 3];        // up-projected vectors  v[n][c][m]
__device__ __align__(16) float g_skip_s[NN * 2 * CC];   // skip_s[n][o]
__device__ __align__(16) float g_skip_v[NN * CC * 3];   // skip_v[n][o][m]
__device__ __align__(16) float g_agg_s[NN * 2 * CC];    // agg_s raw sums
__device__ __align__(16) float g_agg_v[NN * 3 * 2 * CC];// agg_v[n][m][c2] raw sums
__device__ __align__(16) float g_mix[EE * 256];         // per-edge MLP output
__device__ __align__(16) float g_y[EE * 4];             // per-edge sqrt(3)*vhat (w=0)

__device__ __forceinline__ float swishf(float x) { return x / (1.0f + __expf(-x)); }

__device__ __forceinline__ void red4(float* p, float a, float b, float c, float d) {
    asm volatile("red.global.add.v4.f32 [%0], {%1,%2,%3,%4};"
                 :: "l"(p), "f"(a), "f"(b), "f"(c), "f"(d) : "memory");
}

// ---------------- kernel: zero aggregation buffers ----------------
__global__ void k_zero() {
    float4 z = make_float4(0.f, 0.f, 0.f, 0.f);
    int n1 = NN * 2 * CC / 4;
    for (int i = blockIdx.x * blockDim.x + threadIdx.x; i < n1; i += gridDim.x * blockDim.x)
        reinterpret_cast<float4*>(g_agg_s)[i] = z;
    int n2 = NN * 6 * CC / 4;
    for (int i = blockIdx.x * blockDim.x + threadIdx.x; i < n2; i += gridDim.x * blockDim.x)
        reinterpret_cast<float4*>(g_agg_v)[i] = z;
}

// ---------------- kernel: node up-projection ----------------
__global__ void __launch_bounds__(256) k_up(const float* __restrict__ scal,
                                            const float* __restrict__ nvec,
                                            const float* __restrict__ Wus,
                                            const float* __restrict__ Wuv) {
    extern __shared__ float sm[];
    float* sWs = sm;          // 64*64
    float* sWv = sm + 4096;   // 64*64
    float* sBuf = sm + 8192;  // 8 warps * 256
    int tid = threadIdx.x, wid = tid >> 5, l = tid & 31;
    for (int i = tid; i < 4096; i += 256) { sWs[i] = Wus[i]; sWv[i] = Wuv[i]; }
    __syncthreads();
    float* sc = sBuf + wid * 256;
    float* vb = sc + 64;
    int nwarp = gridDim.x * 8;
    for (int n = blockIdx.x * 8 + wid; n < NN; n += nwarp) {
        sc[l] = scal[n * 64 + l];
        sc[l + 32] = scal[n * 64 + l + 32];
#pragma unroll
        for (int q = 0; q < 6; q++) vb[l + q * 32] = nvec[n * 192 + l + q * 32];
        __syncwarp();
        float a0 = 0.f, a1 = 0.f;
#pragma unroll
        for (int k = 0; k < 64; k++) {
            float a = sc[k];
            a0 = fmaf(a, sWs[k * 64 + l], a0);
            a1 = fmaf(a, sWs[k * 64 + l + 32], a1);
        }
        g_s[n * 64 + l] = a0;
        g_s[n * 64 + l + 32] = a1;
        float v0[3] = {0.f, 0.f, 0.f}, v1[3] = {0.f, 0.f, 0.f};
#pragma unroll
        for (int k = 0; k < 64; k++) {
            float w0 = sWv[k * 64 + l], w1 = sWv[k * 64 + l + 32];
#pragma unroll
            for (int m = 0; m < 3; m++) {
                float a = vb[k * 3 + m];
                v0[m] = fmaf(a, w0, v0[m]);
                v1[m] = fmaf(a, w1, v1[m]);
            }
        }
#pragma unroll
        for (int m = 0; m < 3; m++) {
            g_v[n * 192 + l * 3 + m] = v0[m];
            g_v[n * 192 + (l + 32) * 3 + m] = v1[m];
        }
        __syncwarp();
    }
}

// ---------------- kernel: per-species skip projections ----------------
__global__ void __launch_bounds__(256) k_skip(const float* __restrict__ scal,
                                              const float* __restrict__ nvec,
                                              const int* __restrict__ specie,
                                              const float* __restrict__ Wss,
                                              const float* __restrict__ Wsv) {
    extern __shared__ float sm[];
    float* sS = sm;            // 32768
    float* sV = sm + 32768;    // 16384
    float* sBuf = sm + 49152;  // 8 * 256
    int tid = threadIdx.x, wid = tid >> 5, l = tid & 31;
    for (int i = tid; i < 32768; i += 256) sS[i] = Wss[i];
    for (int i = tid; i < 16384; i += 256) sV[i] = Wsv[i];
    __syncthreads();
    float* sc = sBuf + wid * 256;
    float* vb = sc + 64;
    int nwarp = gridDim.x * 8;
    for (int n = blockIdx.x * 8 + wid; n < NN; n += nwarp) {
        sc[l] = scal[n * 64 + l];
        sc[l + 32] = scal[n * 64 + l + 32];
#pragma unroll
        for (int q = 0; q < 6; q++) vb[l + q * 32] = nvec[n * 192 + l + q * 32];
        __syncwarp();
        int sp = specie[n];
        const float* ws = sS + sp * 8192;
        const float* wv = sV + sp * 4096;
        float a0 = 0.f, a1 = 0.f, a2 = 0.f, a3 = 0.f;
#pragma unroll
        for (int k = 0; k < 64; k++) {
            float x = sc[k];
            const float* w = ws + k * 128;
            a0 = fmaf(x, w[l], a0);
            a1 = fmaf(x, w[l + 32], a1);
            a2 = fmaf(x, w[l + 64], a2);
            a3 = fmaf(x, w[l + 96], a3);
        }
        g_skip_s[n * 128 + l] = a0;
        g_skip_s[n * 128 + l + 32] = a1;
        g_skip_s[n * 128 + l + 64] = a2;
        g_skip_s[n * 128 + l + 96] = a3;
        float v0[3] = {0.f, 0.f, 0.f}, v1[3] = {0.f, 0.f, 0.f};
#pragma unroll
        for (int k = 0; k < 64; k++) {
            float w0 = wv[k * 64 + l], w1 = wv[k * 64 + l + 32];
#pragma unroll
            for (int m = 0; m < 3; m++) {
                float a = vb[k * 3 + m];
                v0[m] = fmaf(a, w0, v0[m]);
                v1[m] = fmaf(a, w1, v1[m]);
            }
        }
#pragma unroll
        for (int m = 0; m < 3; m++) {
            g_skip_v[n * 192 + l * 3 + m] = v0[m];
            g_skip_v[n * 192 + (l + 32) * 3 + m] = v1[m];
        }
        __syncwarp();
    }
}

// ---------------- kernel: edge MLP -> g_mix, g_y (unchanged from R9) ----------------
__global__ void __launch_bounds__(256, 2) k_mlp(const float* __restrict__ vectors,
                                                const float* __restrict__ W0,
                                                const float* __restrict__ W1,
                                                const float* __restrict__ W2) {
    extern __shared__ float sm[];
    float* sW0 = sm;                 // 512
    float* sW1 = sm + 512;           // 4096
    float* sW2 = sm + 4608;          // 16384
    float* sH  = sm + 20992;         // 64*65 = 4160, reused H0->H1
    float* sF  = sm + 25152;         // 64*9  = 576  -> total 25728 floats

    int tid = threadIdx.x;
    for (int i = tid; i < 512; i += 256) sW0[i] = W0[i];
    for (int i = tid; i < 4096; i += 256) sW1[i] = W1[i];
    for (int i = tid; i < 16384; i += 256) sW2[i] = W2[i];
    __syncthreads();

    const int og = tid >> 3;  // 0..31
    const int eg = tid & 7;   // 0..7
    const float SQRT2 = 1.41421356237309515f;
    const float SQRT3 = 1.73205080756887729f;
    const float PI = 3.14159265358979323846f;

    int ntile = EE / 64;
    for (int t = blockIdx.x; t < ntile; t += gridDim.x) {
        int e0 = t * 64;
        if (tid < 64) {
            int e = e0 + tid;
            float vx = vectors[e * 3 + 0];
            float vy = vectors[e * 3 + 1];
            float vz = vectors[e * 3 + 2];
            float x = sqrtf(vx * vx + vy * vy + vz * vz);
            float sx = (x == 0.f) ? 1.f : x;
            float inv = 1.f / sx;
            float4 yv = make_float4(SQRT3 * vx * inv, SQRT3 * vy * inv, SQRT3 * vz * inv, 0.f);
            *reinterpret_cast<float4*>(g_y + e * 4) = yv;
            float u = fminf(x, 1.f);
            float u2 = u * u, u3 = u2 * u, u6 = u3 * u3, u7 = u6 * u, u8 = u7 * u;
            float env = (x < 1.f) ? (1.f - 28.f * u6 + 48.f * u7 - 21.f * u8) : 0.f;
            float s1, c1;
            sincosf(PI * x, &s1, &c1);
            float pref = SQRT2 * inv * env;
            float sn = s1, cn = c1;
            sF[tid * 9 + 0] = pref * sn;
#pragma unroll
            for (int b = 1; b < 8; b++) {
                float sn1 = sn * c1 + cn * s1;
                float cn1 = cn * c1 - sn * s1;
                sn = sn1; cn = cn1;
                sF[tid * 9 + b] = pref * sn;
            }
        }
        __syncthreads();

        {
            float a0[8], a1[8];
#pragma unroll
            for (int i = 0; i < 8; i++) { a0[i] = 0.f; a1[i] = 0.f; }
#pragma unroll
            for (int b = 0; b < 8; b++) {
                float w0 = sW0[b * 64 + og];
                float w1 = sW0[b * 64 + og + 32];
#pragma unroll
                for (int i = 0; i < 8; i++) {
                    float f = sF[(eg + 8 * i) * 9 + b];
                    a0[i] = fmaf(f, w0, a0[i]);
                    a1[i] = fmaf(f, w1, a1[i]);
                }
            }
#pragma unroll
            for (int i = 0; i < 8; i++) {
                sH[(eg + 8 * i) * 65 + og] = swishf(a0[i]);
                sH[(eg + 8 * i) * 65 + og + 32] = swishf(a1[i]);
            }
        }
        __syncthreads();

        {
            float a0[8], a1[8];
#pragma unroll
            for (int i = 0; i < 8; i++) { a0[i] = 0.f; a1[i] = 0.f; }
#pragma unroll 2
            for (int k = 0; k < 64; k++) {
                float w0 = sW1[k * 64 + og];
                float w1 = sW1[k * 64 + og + 32];
#pragma unroll
                for (int i = 0; i < 8; i++) {
                    float h = sH[(eg + 8 * i) * 65 + k];
                    a0[i] = fmaf(h, w0, a0[i]);
                    a1[i] = fmaf(h, w1, a1[i]);
                }
            }
            __syncthreads();
#pragma unroll
            for (int i = 0; i < 8; i++) {
                sH[(eg + 8 * i) * 65 + og] = swishf(a0[i]);
                sH[(eg + 8 * i) * 65 + og + 32] = swishf(a1[i]);
            }
        }
        __syncthreads();

        float acc[8][8];
#pragma unroll
        for (int i = 0; i < 8; i++)
#pragma unroll
            for (int q = 0; q < 8; q++) acc[i][q] = 0.f;
        {
            const int j0 = og * 8;
#pragma unroll 2
            for (int k = 0; k < 64; k++) {
                float4 b0 = *reinterpret_cast<const float4*>(sW2 + k * 256 + j0);
                float4 b1 = *reinterpret_cast<const float4*>(sW2 + k * 256 + j0 + 4);
#pragma unroll
                for (int i = 0; i < 8; i++) {
                    float a = sH[(eg + 8 * i) * 65 + k];
                    acc[i][0] = fmaf(a, b0.x, acc[i][0]);
                    acc[i][1] = fmaf(a, b0.y, acc[i][1]);
                    acc[i][2] = fmaf(a, b0.z, acc[i][2]);
                    acc[i][3] = fmaf(a, b0.w, acc[i][3]);
                    acc[i][4] = fmaf(a, b1.x, acc[i][4]);
                    acc[i][5] = fmaf(a, b1.y, acc[i][5]);
                    acc[i][6] = fmaf(a, b1.z, acc[i][6]);
                    acc[i][7] = fmaf(a, b1.w, acc[i][7]);
                }
            }
        }

        {
            const int j0 = og * 8;
#pragma unroll
            for (int i = 0; i < 8; i++) {
                int e = e0 + eg + 8 * i;
                *reinterpret_cast<float4*>(g_mix + e * 256 + j0) =
                    make_float4(acc[i][0], acc[i][1], acc[i][2], acc[i][3]);
                *reinterpret_cast<float4*>(g_mix + e * 256 + j0 + 4) =
                    make_float4(acc[i][4], acc[i][5], acc[i][6], acc[i][7]);
            }
        }
        __syncthreads();
    }
}

// ---------------- kernel: gather + message + scatter (warp-per-edge) ----------------
// Each WARP owns one edge: private smem slice, coalesced loads, __syncwarp only.
// No block-wide barriers -> 8 independent memory pipelines per block.
__global__ void __launch_bounds__(256) k_scatter(const int* __restrict__ senders,
                                                 const int* __restrict__ receivers) {
    __shared__ float sb[8][520];  // per warp: S[64] V[192] M[256] Y[4] (+pad)
    int tid = threadIdx.x;
    int w = tid >> 5, l = tid & 31;
    const float INV_SQRT3 = 0.57735026918962576f;
    float* S = sb[w];
    float* V = S + 64;
    float* M = V + 192;
    float* Yp = M + 256;
    int nwarp = gridDim.x * 8;
    for (int e = blockIdx.x * 8 + w; e < EE; e += nwarp) {
        int snd = senders[e];
        int rcv = receivers[e];
        // mix: 64 float4, 2 per lane (coalesced 1KB)
        *reinterpret_cast<float4*>(M + l * 4) =
            *reinterpret_cast<const float4*>(g_mix + e * 256 + l * 4);
        *reinterpret_cast<float4*>(M + (l + 32) * 4) =
            *reinterpret_cast<const float4*>(g_mix + e * 256 + (l + 32) * 4);
        // v: 48 float4
        *reinterpret_cast<float4*>(V + l * 4) =
            *reinterpret_cast<const float4*>(g_v + snd * 192 + l * 4);
        if (l < 16)
            *reinterpret_cast<float4*>(V + (l + 32) * 4) =
                *reinterpret_cast<const float4*>(g_v + snd * 192 + (l + 32) * 4);
        // s: 16 float4
        if (l < 16)
            *reinterpret_cast<float4*>(S + l * 4) =
                *reinterpret_cast<const float4*>(g_s + snd * 64 + l * 4);
        if (l == 0)
            *reinterpret_cast<float4*>(Yp) = *reinterpret_cast<const float4*>(g_y + e * 4);
        __syncwarp();

#pragma unroll
        for (int j = 0; j < 4; j++) {
            int o = l + 32 * j;  // 0..127
            if (o < 16) {
                int c = o * 4;
                red4(g_agg_s + rcv * 128 + c,
                     S[c] * M[c], S[c + 1] * M[c + 1],
                     S[c + 2] * M[c + 2], S[c + 3] * M[c + 3]);
            } else if (o < 32) {
                int c = (o - 16) * 4;
                float y0 = Yp[0], y1 = Yp[1], y2 = Yp[2];
                float v[4];
#pragma unroll
                for (int t = 0; t < 4; t++) {
                    int cc = c + t;
                    v[t] = (V[cc * 3] * y0 + V[cc * 3 + 1] * y1 + V[cc * 3 + 2] * y2)
                           * INV_SQRT3 * M[64 + cc];
                }
                red4(g_agg_s + rcv * 128 + 64 + c, v[0], v[1], v[2], v[3]);
            } else {
                int q = o - 32;          // 0..95
                int m = q >> 5, cb = q & 31;
                int c2 = cb * 4;
                float v[4];
                if (c2 < 64) {
#pragma unroll
                    for (int t = 0; t < 4; t++)
                        v[t] = V[(c2 + t) * 3 + m] * M[128 + c2 + t];
                } else {
                    int c = c2 - 64;
                    float ym = Yp[m];
#pragma unroll
                    for (int t = 0; t < 4; t++)
                        v[t] = S[c + t] * ym * M[192 + c + t];
                }
                red4(g_agg_v + rcv * 384 + m * 128 + c2, v[0], v[1], v[2], v[3]);
            }
        }
        __syncwarp();  // protect smem slice before next edge
    }
}

// ---------------- kernel: final down-projection + skip + gating + output ----------------
__global__ void __launch_bounds__(256) k_final(const float* __restrict__ Wds,
                                               const float* __restrict__ Wdv,
                                               float* __restrict__ out) {
    extern __shared__ float sm[];
    float* sWs = sm;            // 16384
    float* sWv = sm + 16384;    // 8192
    float* sBuf = sm + 24576;   // 8 * 520
    int tid = threadIdx.x, wid = tid >> 5, l = tid & 31;
    for (int i = tid; i < 16384; i += 256) sWs[i] = Wds[i];
    for (int i = tid; i < 8192; i += 256) sWv[i] = Wdv[i];
    __syncthreads();
    float* As = sBuf + wid * 520;
    float* Av = As + 128;
    const float INV = 0.25f;
    int nwarp = gridDim.x * 8;
    for (int n = blockIdx.x * 8 + wid; n < NN; n += nwarp) {
#pragma unroll
        for (int q = 0; q < 4; q++) As[l + 32 * q] = g_agg_s[n * 128 + l + 32 * q];
#pragma unroll
        for (int q = 0; q < 12; q++) Av[l + 32 * q] = g_agg_v[n * 384 + l + 32 * q];
        __syncwarp();
        float a0 = 0.f, a1 = 0.f, a2 = 0.f, a3 = 0.f;
#pragma unroll 4
        for (int k = 0; k < 128; k++) {
            float x = As[k];
            const float* w = sWs + k * 128;
            a0 = fmaf(x, w[l], a0);
            a1 = fmaf(x, w[l + 32], a1);
            a2 = fmaf(x, w[l + 64], a2);
            a3 = fmaf(x, w[l + 96], a3);
        }
        float os0 = INV * a0 + g_skip_s[n * 128 + l];
        float os1 = INV * a1 + g_skip_s[n * 128 + l + 32];
        float os2 = INV * a2 + g_skip_s[n * 128 + l + 64];
        float os3 = INV * a3 + g_skip_s[n * 128 + l + 96];
        float scal0 = swishf(os0), scal1 = swishf(os1);
        float gate0 = swishf(os2), gate1 = swishf(os3);
        float v0[3] = {0.f, 0.f, 0.f}, v1[3] = {0.f, 0.f, 0.f};
#pragma unroll 4
        for (int k = 0; k < 128; k++) {
            float w0 = sWv[k * 64 + l], w1 = sWv[k * 64 + l + 32];
#pragma unroll
            for (int m = 0; m < 3; m++) {
                float a = Av[m * 128 + k];
                v0[m] = fmaf(a, w0, v0[m]);
                v1[m] = fmaf(a, w1, v1[m]);
            }
        }
        out[n * 256 + l] = scal0;
        out[n * 256 + l + 32] = scal1;
#pragma unroll
        for (int m = 0; m < 3; m++) {
            float ov0 = INV * v0[m] + g_skip_v[n * 192 + l * 3 + m];
            float ov1 = INV * v1[m] + g_skip_v[n * 192 + (l + 32) * 3 + m];
            out[n * 256 + 64 + l * 3 + m] = ov0 * gate0;
            out[n * 256 + 64 + (l + 32) * 3 + m] = ov1 * gate1;
        }
        __syncwarp();
    }
}

// ---------------- launch ----------------
extern "C" void kernel_launch(void* const* d_in, const int* in_sizes, int n_in,
                              void* d_out, int out_size) {
    const float* vectors      = (const float*)d_in[0];
    const float* node_scalars = (const float*)d_in[1];
    const float* node_vectors = (const float*)d_in[2];
    const int*   node_specie  = (const int*)d_in[3];
    const int*   senders      = (const int*)d_in[4];
    const int*   receivers    = (const int*)d_in[5];
    const float* W_skip_s     = (const float*)d_in[6];
    const float* W_skip_v     = (const float*)d_in[7];
    const float* W_up_s       = (const float*)d_in[8];
    const float* W_up_v       = (const float*)d_in[9];
    const float* W_mlp0       = (const float*)d_in[10];
    const float* W_mlp1       = (const float*)d_in[11];
    const float* W_mlp2       = (const float*)d_in[12];
    const float* W_down_s     = (const float*)d_in[13];
    const float* W_down_v     = (const float*)d_in[14];
    float* out = (float*)d_out;

    const int UP_SMEM    = (8192 + 8 * 256) * 4;            // 40 KB
    const int SKIP_SMEM  = (49152 + 8 * 256) * 4;           // 200 KB
    const int MLP_SMEM   = 25728 * 4;                       // ~100.5 KB -> 2 blocks/SM
    const int FINAL_SMEM = (24576 + 8 * 520) * 4;           // ~114.5 KB

    cudaFuncSetAttribute(k_skip,  cudaFuncAttributeMaxDynamicSharedMemorySize, SKIP_SMEM);
    cudaFuncSetAttribute(k_mlp,   cudaFuncAttributeMaxDynamicSharedMemorySize, MLP_SMEM);
    cudaFuncSetAttribute(k_final, cudaFuncAttributeMaxDynamicSharedMemorySize, FINAL_SMEM);

    k_zero<<<2048, 256>>>();
    k_up<<<512, 256, UP_SMEM>>>(node_scalars, node_vectors, W_up_s, W_up_v);
    k_skip<<<296, 256, SKIP_SMEM>>>(node_scalars, node_vectors, node_specie, W_skip_s, W_skip_v);
    k_mlp<<<296, 256, MLP_SMEM>>>(vectors, W_mlp0, W_mlp1, W_mlp2);
    k_scatter<<<2960, 256>>>(senders, receivers);
    k_final<<<296, 256, FINAL_SMEM>>>(W_down_s, W_down_v, out);
}

// round 13
// speedup vs baseline: 1.8019x; 1.0431x over previous
#include <cuda_runtime.h>
#include <math.h>

// Problem constants (fixed shapes)
#define NN 20000
#define EE 320000
#define CC 64

// ---------------- scratch (device globals; no allocation allowed) ----------------
__device__ __align__(16) float g_s[NN * CC];            // up-projected scalars  s[n][c]
__device__ __align__(16) float g_v[NN * CC * 3];        // up-projected vectors  v[n][c][m]
__device__ __align__(16) float g_skip_s[NN * 2 * CC];   // skip_s[n][o]
__device__ __align__(16) float g_skip_v[NN * CC * 3];   // skip_v[n][o][m]
__device__ __align__(16) float g_agg_s[NN * 2 * CC];    // agg_s raw sums
__device__ __align__(16) float g_agg_v[NN * 3 * 2 * CC];// agg_v[n][m][c2] raw sums
__device__ __align__(16) float g_mix[EE * 256];         // per-edge MLP output
__device__ __align__(16) float g_y[EE * 4];             // per-edge sqrt(3)*vhat (w=0)

__device__ __forceinline__ float swishf(float x) { return x / (1.0f + __expf(-x)); }

__device__ __forceinline__ void red4(float* p, float a, float b, float c, float d) {
    asm volatile("red.global.add.v4.f32 [%0], {%1,%2,%3,%4};"
                 :: "l"(p), "f"(a), "f"(b), "f"(c), "f"(d) : "memory");
}

// ---- packed f32x2 helpers (Blackwell FFMA2 path) ----
__device__ __forceinline__ unsigned long long dup2(float a) {
    unsigned long long r;
    asm("mov.b64 %0, {%1,%1};" : "=l"(r) : "f"(a));
    return r;
}
__device__ __forceinline__ unsigned long long ffma2(unsigned long long a,
                                                    unsigned long long b,
                                                    unsigned long long c) {
    unsigned long long d;
    asm("fma.rn.f32x2 %0, %1, %2, %3;" : "=l"(d) : "l"(a), "l"(b), "l"(c));
    return d;
}
__device__ __forceinline__ float2 unpack2(unsigned long long v) {
    float2 f;
    asm("mov.b64 {%0,%1}, %2;" : "=f"(f.x), "=f"(f.y) : "l"(v));
    return f;
}

// ---------------- kernel: zero aggregation buffers ----------------
__global__ void k_zero() {
    float4 z = make_float4(0.f, 0.f, 0.f, 0.f);
    int n1 = NN * 2 * CC / 4;
    for (int i = blockIdx.x * blockDim.x + threadIdx.x; i < n1; i += gridDim.x * blockDim.x)
        reinterpret_cast<float4*>(g_agg_s)[i] = z;
    int n2 = NN * 6 * CC / 4;
    for (int i = blockIdx.x * blockDim.x + threadIdx.x; i < n2; i += gridDim.x * blockDim.x)
        reinterpret_cast<float4*>(g_agg_v)[i] = z;
}

// ---------------- kernel: node up-projection ----------------
__global__ void __launch_bounds__(256) k_up(const float* __restrict__ scal,
                                            const float* __restrict__ nvec,
                                            const float* __restrict__ Wus,
                                            const float* __restrict__ Wuv) {
    extern __shared__ float sm[];
    float* sWs = sm;          // 64*64
    float* sWv = sm + 4096;   // 64*64
    float* sBuf = sm + 8192;  // 8 warps * 256
    int tid = threadIdx.x, wid = tid >> 5, l = tid & 31;
    for (int i = tid; i < 4096; i += 256) { sWs[i] = Wus[i]; sWv[i] = Wuv[i]; }
    __syncthreads();
    float* sc = sBuf + wid * 256;
    float* vb = sc + 64;
    int nwarp = gridDim.x * 8;
    for (int n = blockIdx.x * 8 + wid; n < NN; n += nwarp) {
        sc[l] = scal[n * 64 + l];
        sc[l + 32] = scal[n * 64 + l + 32];
#pragma unroll
        for (int q = 0; q < 6; q++) vb[l + q * 32] = nvec[n * 192 + l + q * 32];
        __syncwarp();
        float a0 = 0.f, a1 = 0.f;
#pragma unroll
        for (int k = 0; k < 64; k++) {
            float a = sc[k];
            a0 = fmaf(a, sWs[k * 64 + l], a0);
            a1 = fmaf(a, sWs[k * 64 + l + 32], a1);
        }
        g_s[n * 64 + l] = a0;
        g_s[n * 64 + l + 32] = a1;
        float v0[3] = {0.f, 0.f, 0.f}, v1[3] = {0.f, 0.f, 0.f};
#pragma unroll
        for (int k = 0; k < 64; k++) {
            float w0 = sWv[k * 64 + l], w1 = sWv[k * 64 + l + 32];
#pragma unroll
            for (int m = 0; m < 3; m++) {
                float a = vb[k * 3 + m];
                v0[m] = fmaf(a, w0, v0[m]);
                v1[m] = fmaf(a, w1, v1[m]);
            }
        }
#pragma unroll
        for (int m = 0; m < 3; m++) {
            g_v[n * 192 + l * 3 + m] = v0[m];
            g_v[n * 192 + (l + 32) * 3 + m] = v1[m];
        }
        __syncwarp();
    }
}

// ---------------- kernel: per-species skip projections ----------------
__global__ void __launch_bounds__(256) k_skip(const float* __restrict__ scal,
                                              const float* __restrict__ nvec,
                                              const int* __restrict__ specie,
                                              const float* __restrict__ Wss,
                                              const float* __restrict__ Wsv) {
    extern __shared__ float sm[];
    float* sS = sm;            // 32768
    float* sV = sm + 32768;    // 16384
    float* sBuf = sm + 49152;  // 8 * 256
    int tid = threadIdx.x, wid = tid >> 5, l = tid & 31;
    for (int i = tid; i < 32768; i += 256) sS[i] = Wss[i];
    for (int i = tid; i < 16384; i += 256) sV[i] = Wsv[i];
    __syncthreads();
    float* sc = sBuf + wid * 256;
    float* vb = sc + 64;
    int nwarp = gridDim.x * 8;
    for (int n = blockIdx.x * 8 + wid; n < NN; n += nwarp) {
        sc[l] = scal[n * 64 + l];
        sc[l + 32] = scal[n * 64 + l + 32];
#pragma unroll
        for (int q = 0; q < 6; q++) vb[l + q * 32] = nvec[n * 192 + l + q * 32];
        __syncwarp();
        int sp = specie[n];
        const float* ws = sS + sp * 8192;
        const float* wv = sV + sp * 4096;
        float a0 = 0.f, a1 = 0.f, a2 = 0.f, a3 = 0.f;
#pragma unroll
        for (int k = 0; k < 64; k++) {
            float x = sc[k];
            const float* w = ws + k * 128;
            a0 = fmaf(x, w[l], a0);
            a1 = fmaf(x, w[l + 32], a1);
            a2 = fmaf(x, w[l + 64], a2);
            a3 = fmaf(x, w[l + 96], a3);
        }
        g_skip_s[n * 128 + l] = a0;
        g_skip_s[n * 128 + l + 32] = a1;
        g_skip_s[n * 128 + l + 64] = a2;
        g_skip_s[n * 128 + l + 96] = a3;
        float v0[3] = {0.f, 0.f, 0.f}, v1[3] = {0.f, 0.f, 0.f};
#pragma unroll
        for (int k = 0; k < 64; k++) {
            float w0 = wv[k * 64 + l], w1 = wv[k * 64 + l + 32];
#pragma unroll
            for (int m = 0; m < 3; m++) {
                float a = vb[k * 3 + m];
                v0[m] = fmaf(a, w0, v0[m]);
                v1[m] = fmaf(a, w1, v1[m]);
            }
        }
#pragma unroll
        for (int m = 0; m < 3; m++) {
            g_skip_v[n * 192 + l * 3 + m] = v0[m];
            g_skip_v[n * 192 + (l + 32) * 3 + m] = v1[m];
        }
        __syncwarp();
    }
}

// ---------------- kernel: edge MLP -> g_mix, g_y ----------------
// Same structure as R9/R11 ([e][65] layout, conflict-free e = eg+8*i map),
// but phases 3/4 use FFMA2 paired over OUTPUT columns: weight pairs are
// naturally contiguous 64-bit smem words (no packing); the broadcast
// activation is duplicated with one mov.b64 (ALU pipe). Halves fma-pipe
// issue on the 2 dominant GEMMs.
__global__ void __launch_bounds__(256, 2) k_mlp(const float* __restrict__ vectors,
                                                const float* __restrict__ W0,
                                                const float* __restrict__ W1,
                                                const float* __restrict__ W2) {
    extern __shared__ float sm[];
    float* sW0 = sm;                 // 512
    float* sW1 = sm + 512;           // 4096
    float* sW2 = sm + 4608;          // 16384
    float* sH  = sm + 20992;         // 64*65 = 4160, reused H0->H1
    float* sF  = sm + 25152;         // 64*9  = 576  -> total 25728 floats

    int tid = threadIdx.x;
    for (int i = tid; i < 512; i += 256) sW0[i] = W0[i];
    for (int i = tid; i < 4096; i += 256) sW1[i] = W1[i];
    for (int i = tid; i < 16384; i += 256) sW2[i] = W2[i];
    __syncthreads();

    const int og = tid >> 3;  // 0..31
    const int eg = tid & 7;   // 0..7
    const float SQRT2 = 1.41421356237309515f;
    const float SQRT3 = 1.73205080756887729f;
    const float PI = 3.14159265358979323846f;

    int ntile = EE / 64;
    for (int t = blockIdx.x; t < ntile; t += gridDim.x) {
        int e0 = t * 64;
        // ---- phase 1: per-edge features (threads 0..63) ----
        if (tid < 64) {
            int e = e0 + tid;
            float vx = vectors[e * 3 + 0];
            float vy = vectors[e * 3 + 1];
            float vz = vectors[e * 3 + 2];
            float x = sqrtf(vx * vx + vy * vy + vz * vz);
            float sx = (x == 0.f) ? 1.f : x;
            float inv = 1.f / sx;
            float4 yv = make_float4(SQRT3 * vx * inv, SQRT3 * vy * inv, SQRT3 * vz * inv, 0.f);
            *reinterpret_cast<float4*>(g_y + e * 4) = yv;
            float u = fminf(x, 1.f);
            float u2 = u * u, u3 = u2 * u, u6 = u3 * u3, u7 = u6 * u, u8 = u7 * u;
            float env = (x < 1.f) ? (1.f - 28.f * u6 + 48.f * u7 - 21.f * u8) : 0.f;
            float s1, c1;
            sincosf(PI * x, &s1, &c1);
            float pref = SQRT2 * inv * env;
            float sn = s1, cn = c1;
            sF[tid * 9 + 0] = pref * sn;
#pragma unroll
            for (int b = 1; b < 8; b++) {
                float sn1 = sn * c1 + cn * s1;
                float cn1 = cn * c1 - sn * s1;
                sn = sn1; cn = cn1;
                sF[tid * 9 + b] = pref * sn;
            }
        }
        __syncthreads();

        // ---- phase 2: h0 = swish(feat @ W0) (scalar, small) ----
        {
            float a0[8], a1[8];
#pragma unroll
            for (int i = 0; i < 8; i++) { a0[i] = 0.f; a1[i] = 0.f; }
#pragma unroll
            for (int b = 0; b < 8; b++) {
                float w0 = sW0[b * 64 + og];
                float w1 = sW0[b * 64 + og + 32];
#pragma unroll
                for (int i = 0; i < 8; i++) {
                    float f = sF[(eg + 8 * i) * 9 + b];
                    a0[i] = fmaf(f, w0, a0[i]);
                    a1[i] = fmaf(f, w1, a1[i]);
                }
            }
#pragma unroll
            for (int i = 0; i < 8; i++) {
                sH[(eg + 8 * i) * 65 + og] = swishf(a0[i]);
                sH[(eg + 8 * i) * 65 + og + 32] = swishf(a1[i]);
            }
        }
        __syncthreads();

        // ---- phase 3: h1 = swish(h0 @ W1), FFMA2 over output pair (2og, 2og+1) ----
        {
            unsigned long long acc[8];
#pragma unroll
            for (int i = 0; i < 8; i++) acc[i] = 0ULL;
            const unsigned long long* w1p =
                reinterpret_cast<const unsigned long long*>(sW1 + 2 * og);
#pragma unroll 2
            for (int k = 0; k < 64; k++) {
                unsigned long long wp = w1p[k * 32];  // (W1[k][2og], W1[k][2og+1])
#pragma unroll
                for (int i = 0; i < 8; i++) {
                    unsigned long long ad = dup2(sH[(eg + 8 * i) * 65 + k]);
                    acc[i] = ffma2(ad, wp, acc[i]);
                }
            }
            __syncthreads();  // everyone done READING h0 before in-place overwrite
#pragma unroll
            for (int i = 0; i < 8; i++) {
                float2 f = unpack2(acc[i]);
                sH[(eg + 8 * i) * 65 + 2 * og] = swishf(f.x);
                sH[(eg + 8 * i) * 65 + 2 * og + 1] = swishf(f.y);
            }
        }
        __syncthreads();

        // ---- phase 4: mix = h1 @ W2, FFMA2, thread tile 8e x 4 j-pairs ----
        unsigned long long acc[8][4];
#pragma unroll
        for (int i = 0; i < 8; i++)
#pragma unroll
            for (int q = 0; q < 4; q++) acc[i][q] = 0ULL;
        {
            const int j0 = og * 8;
#pragma unroll 2
            for (int k = 0; k < 64; k++) {
                ulonglong2 b0 = *reinterpret_cast<const ulonglong2*>(sW2 + k * 256 + j0);
                ulonglong2 b1 = *reinterpret_cast<const ulonglong2*>(sW2 + k * 256 + j0 + 4);
#pragma unroll
                for (int i = 0; i < 8; i++) {
                    unsigned long long ad = dup2(sH[(eg + 8 * i) * 65 + k]);
                    acc[i][0] = ffma2(ad, b0.x, acc[i][0]);
                    acc[i][1] = ffma2(ad, b0.y, acc[i][1]);
                    acc[i][2] = ffma2(ad, b1.x, acc[i][2]);
                    acc[i][3] = ffma2(ad, b1.y, acc[i][3]);
                }
            }
        }

        // ---- phase 5': store mix coalesced (u64 pairs = consecutive j floats) ----
        {
            const int j0 = og * 8;
#pragma unroll
            for (int i = 0; i < 8; i++) {
                int e = e0 + eg + 8 * i;
                ulonglong2 lo, hi;
                lo.x = acc[i][0]; lo.y = acc[i][1];
                hi.x = acc[i][2]; hi.y = acc[i][3];
                *reinterpret_cast<ulonglong2*>(g_mix + e * 256 + j0) = lo;
                *reinterpret_cast<ulonglong2*>(g_mix + e * 256 + j0 + 4) = hi;
            }
        }
        __syncthreads();
    }
}

// ---------------- kernel: gather + message + scatter (warp-per-edge) ----------------
__global__ void __launch_bounds__(256) k_scatter(const int* __restrict__ senders,
                                                 const int* __restrict__ receivers) {
    __shared__ float sb[8][520];  // per warp: S[64] V[192] M[256] Y[4] (+pad)
    int tid = threadIdx.x;
    int w = tid >> 5, l = tid & 31;
    const float INV_SQRT3 = 0.57735026918962576f;
    float* S = sb[w];
    float* V = S + 64;
    float* M = V + 192;
    float* Yp = M + 256;
    int nwarp = gridDim.x * 8;
    for (int e = blockIdx.x * 8 + w; e < EE; e += nwarp) {
        int snd = senders[e];
        int rcv = receivers[e];
        *reinterpret_cast<float4*>(M + l * 4) =
            *reinterpret_cast<const float4*>(g_mix + e * 256 + l * 4);
        *reinterpret_cast<float4*>(M + (l + 32) * 4) =
            *reinterpret_cast<const float4*>(g_mix + e * 256 + (l + 32) * 4);
        *reinterpret_cast<float4*>(V + l * 4) =
            *reinterpret_cast<const float4*>(g_v + snd * 192 + l * 4);
        if (l < 16)
            *reinterpret_cast<float4*>(V + (l + 32) * 4) =
                *reinterpret_cast<const float4*>(g_v + snd * 192 + (l + 32) * 4);
        if (l < 16)
            *reinterpret_cast<float4*>(S + l * 4) =
                *reinterpret_cast<const float4*>(g_s + snd * 64 + l * 4);
        if (l == 0)
            *reinterpret_cast<float4*>(Yp) = *reinterpret_cast<const float4*>(g_y + e * 4);
        __syncwarp();

#pragma unroll
        for (int j = 0; j < 4; j++) {
            int o = l + 32 * j;  // 0..127
            if (o < 16) {
                int c = o * 4;
                red4(g_agg_s + rcv * 128 + c,
                     S[c] * M[c], S[c + 1] * M[c + 1],
                     S[c + 2] * M[c + 2], S[c + 3] * M[c + 3]);
            } else if (o < 32) {
                int c = (o - 16) * 4;
                float y0 = Yp[0], y1 = Yp[1], y2 = Yp[2];
                float v[4];
#pragma unroll
                for (int t = 0; t < 4; t++) {
                    int cc = c + t;
                    v[t] = (V[cc * 3] * y0 + V[cc * 3 + 1] * y1 + V[cc * 3 + 2] * y2)
                           * INV_SQRT3 * M[64 + cc];
                }
                red4(g_agg_s + rcv * 128 + 64 + c, v[0], v[1], v[2], v[3]);
            } else {
                int q = o - 32;          // 0..95
                int m = q >> 5, cb = q & 31;
                int c2 = cb * 4;
                float v[4];
                if (c2 < 64) {
#pragma unroll
                    for (int t = 0; t < 4; t++)
                        v[t] = V[(c2 + t) * 3 + m] * M[128 + c2 + t];
                } else {
                    int c = c2 - 64;
                    float ym = Yp[m];
#pragma unroll
                    for (int t = 0; t < 4; t++)
                        v[t] = S[c + t] * ym * M[192 + c + t];
                }
                red4(g_agg_v + rcv * 384 + m * 128 + c2, v[0], v[1], v[2], v[3]);
            }
        }
        __syncwarp();
    }
}

// ---------------- kernel: final down-projection + skip + gating + output ----------------
__global__ void __launch_bounds__(256) k_final(const float* __restrict__ Wds,
                                               const float* __restrict__ Wdv,
                                               float* __restrict__ out) {
    extern __shared__ float sm[];
    float* sWs = sm;            // 16384
    float* sWv = sm + 16384;    // 8192
    float* sBuf = sm + 24576;   // 8 * 520
    int tid = threadIdx.x, wid = tid >> 5, l = tid & 31;
    for (int i = tid; i < 16384; i += 256) sWs[i] = Wds[i];
    for (int i = tid; i < 8192; i += 256) sWv[i] = Wdv[i];
    __syncthreads();
    float* As = sBuf + wid * 520;
    float* Av = As + 128;
    const float INV = 0.25f;
    int nwarp = gridDim.x * 8;
    for (int n = blockIdx.x * 8 + wid; n < NN; n += nwarp) {
#pragma unroll
        for (int q = 0; q < 4; q++) As[l + 32 * q] = g_agg_s[n * 128 + l + 32 * q];
#pragma unroll
        for (int q = 0; q < 12; q++) Av[l + 32 * q] = g_agg_v[n * 384 + l + 32 * q];
        __syncwarp();
        float a0 = 0.f, a1 = 0.f, a2 = 0.f, a3 = 0.f;
#pragma unroll 4
        for (int k = 0; k < 128; k++) {
            float x = As[k];
            const float* w = sWs + k * 128;
            a0 = fmaf(x, w[l], a0);
            a1 = fmaf(x, w[l + 32], a1);
            a2 = fmaf(x, w[l + 64], a2);
            a3 = fmaf(x, w[l + 96], a3);
        }
        float os0 = INV * a0 + g_skip_s[n * 128 + l];
        float os1 = INV * a1 + g_skip_s[n * 128 + l + 32];
        float os2 = INV * a2 + g_skip_s[n * 128 + l + 64];
        float os3 = INV * a3 + g_skip_s[n * 128 + l + 96];
        float scal0 = swishf(os0), scal1 = swishf(os1);
        float gate0 = swishf(os2), gate1 = swishf(os3);
        float v0[3] = {0.f, 0.f, 0.f}, v1[3] = {0.f, 0.f, 0.f};
#pragma unroll 4
        for (int k = 0; k < 128; k++) {
            float w0 = sWv[k * 64 + l], w1 = sWv[k * 64 + l + 32];
#pragma unroll
            for (int m = 0; m < 3; m++) {
                float a = Av[m * 128 + k];
                v0[m] = fmaf(a, w0, v0[m]);
                v1[m] = fmaf(a, w1, v1[m]);
            }
        }
        out[n * 256 + l] = scal0;
        out[n * 256 + l + 32] = scal1;
#pragma unroll
        for (int m = 0; m < 3; m++) {
            float ov0 = INV * v0[m] + g_skip_v[n * 192 + l * 3 + m];
            float ov1 = INV * v1[m] + g_skip_v[n * 192 + (l + 32) * 3 + m];
            out[n * 256 + 64 + l * 3 + m] = ov0 * gate0;
            out[n * 256 + 64 + (l + 32) * 3 + m] = ov1 * gate1;
        }
        __syncwarp();
    }
}

// ---------------- launch ----------------
extern "C" void kernel_launch(void* const* d_in, const int* in_sizes, int n_in,
                              void* d_out, int out_size) {
    const float* vectors      = (const float*)d_in[0];
    const float* node_scalars = (const float*)d_in[1];
    const float* node_vectors = (const float*)d_in[2];
    const int*   node_specie  = (const int*)d_in[3];
    const int*   senders      = (const int*)d_in[4];
    const int*   receivers    = (const int*)d_in[5];
    const float* W_skip_s     = (const float*)d_in[6];
    const float* W_skip_v     = (const float*)d_in[7];
    const float* W_up_s       = (const float*)d_in[8];
    const float* W_up_v       = (const float*)d_in[9];
    const float* W_mlp0       = (const float*)d_in[10];
    const float* W_mlp1       = (const float*)d_in[11];
    const float* W_mlp2       = (const float*)d_in[12];
    const float* W_down_s     = (const float*)d_in[13];
    const float* W_down_v     = (const float*)d_in[14];
    float* out = (float*)d_out;

    const int UP_SMEM    = (8192 + 8 * 256) * 4;            // 40 KB
    const int SKIP_SMEM  = (49152 + 8 * 256) * 4;           // 200 KB
    const int MLP_SMEM   = 25728 * 4;                       // ~100.5 KB -> 2 blocks/SM
    const int FINAL_SMEM = (24576 + 8 * 520) * 4;           // ~114.5 KB

    cudaFuncSetAttribute(k_skip,  cudaFuncAttributeMaxDynamicSharedMemorySize, SKIP_SMEM);
    cudaFuncSetAttribute(k_mlp,   cudaFuncAttributeMaxDynamicSharedMemorySize, MLP_SMEM);
    cudaFuncSetAttribute(k_final, cudaFuncAttributeMaxDynamicSharedMemorySize, FINAL_SMEM);

    k_zero<<<2048, 256>>>();
    k_up<<<512, 256, UP_SMEM>>>(node_scalars, node_vectors, W_up_s, W_up_v);
    k_skip<<<296, 256, SKIP_SMEM>>>(node_scalars, node_vectors, node_specie, W_skip_s, W_skip_v);
    k_mlp<<<296, 256, MLP_SMEM>>>(vectors, W_mlp0, W_mlp1, W_mlp2);
    k_scatter<<<2960, 256>>>(senders, receivers);
    k_final<<<296, 256, FINAL_SMEM>>>(W_down_s, W_down_v, out);
}